// round 9
// baseline (speedup 1.0000x reference)
#include <cuda_runtime.h>
#include <cuda_bf16.h>
#include <cstdint>
#include <cstddef>

typedef unsigned int u32;

#define BN 4
#define TT 2048
#define CC 1024
#define MROWS (BN*TT)   // 8192

// ======================= device scratch (no allocs allowed) =======================
__device__ __align__(256) __nv_bfloat16 g_xh[MROWS*CC];
__device__ __align__(256) __nv_bfloat16 g_xl[MROWS*CC];
__device__ __align__(256) __nv_bfloat16 g_wh[4*CC*CC];
__device__ __align__(256) __nv_bfloat16 g_wl[4*CC*CC];
__device__ __align__(256) __nv_bfloat16 g_qh[MROWS*CC];
__device__ __align__(256) __nv_bfloat16 g_ql[MROWS*CC];
__device__ __align__(256) __nv_bfloat16 g_kh[MROWS*CC];
__device__ __align__(256) __nv_bfloat16 g_kl[MROWS*CC];
__device__ __align__(256) __nv_bfloat16 g_vth[MROWS*CC];  // V^T: [b][d][s]
__device__ __align__(256) __nv_bfloat16 g_vtl[MROWS*CC];
__device__ __align__(256) float         g_s [(size_t)BN*TT*TT];
__device__ __align__(256) __nv_bfloat16 g_ph[(size_t)BN*TT*TT];
__device__ __align__(256) __nv_bfloat16 g_pl[(size_t)BN*TT*TT];
__device__ __align__(256) __nv_bfloat16 g_ch[MROWS*CC];
__device__ __align__(256) __nv_bfloat16 g_cl[MROWS*CC];

// ======================= PTX helpers (sm_100 baseline, NO 'a' features) =======================
__device__ __forceinline__ u32 smem_u32(const void* p) {
    u32 a;
    asm("{ .reg .u64 t; cvta.to.shared.u64 t, %1; cvt.u32.u64 %0, t; }" : "=r"(a) : "l"(p));
    return a;
}
__device__ __forceinline__ void cpa16(u32 dst, const void* src) {
    asm volatile("cp.async.cg.shared.global [%0], [%1], 16;" :: "r"(dst), "l"(src) : "memory");
}
#define CP_COMMIT() asm volatile("cp.async.commit_group;" ::: "memory")
#define CP_WAIT(n)  asm volatile("cp.async.wait_group %0;" :: "n"(n) : "memory")

#define LDSM4(d0,d1,d2,d3,a) \
    asm volatile("ldmatrix.sync.aligned.m8n8.x4.shared.b16 {%0,%1,%2,%3}, [%4];" \
                 : "=r"(d0),"=r"(d1),"=r"(d2),"=r"(d3) : "r"(a))
#define LDSM2(d0,d1,a) \
    asm volatile("ldmatrix.sync.aligned.m8n8.x2.shared.b16 {%0,%1}, [%2];" \
                 : "=r"(d0),"=r"(d1) : "r"(a))

__device__ __forceinline__ void mma16816(float* c, const u32* a, const u32* b) {
    asm volatile(
        "mma.sync.aligned.m16n8k16.row.col.f32.bf16.bf16.f32 "
        "{%0,%1,%2,%3}, {%4,%5,%6,%7}, {%8,%9}, {%0,%1,%2,%3};"
        : "+f"(c[0]), "+f"(c[1]), "+f"(c[2]), "+f"(c[3])
        : "r"(a[0]), "r"(a[1]), "r"(a[2]), "r"(a[3]), "r"(b[0]), "r"(b[1]));
}

__device__ __forceinline__ u32 pack_bf2(__nv_bfloat16 a, __nv_bfloat16 b) {
    __nv_bfloat162 t = __halves2bfloat162(a, b);
    return *reinterpret_cast<u32*>(&t);
}
__device__ __forceinline__ unsigned short bf_bits(__nv_bfloat16 h) {
    return *reinterpret_cast<unsigned short*>(&h);
}

// 64B-row swizzle: row*64 + ((c16 ^ ((row>>1)&3)) << 4); bijective over the 8
// 16B slots per 128B phase; additive in row steps of 8/16 -> LDSM addresses
// collapse to base + constant.
__device__ __forceinline__ u32 swz64(int row, int c16) {
    return (u32)row * 64u + (u32)((c16 ^ ((row >> 1) & 3)) << 4);
}

// ======================= GEMM kernel =======================
// Tile 128x128, K-chunk 32. Stage: Ah(8K) Al(8K) Bh(8K) Bl(8K) = 32KB; 3 stages.
// 2 CTAs/SM (regs capped at 128, smem 97KB/CTA).
#define ST_BYTES   32768u
#define NSTAGE     3
#define SMEM_BYTES (1024 + NSTAGE*32768)   // 99328

// MODE 0: split bf16 hi/lo row-major (+optional bias, +batch stride on C)
// MODE 1: V-projection: bias then transposed split store into vt[b][d][s]
// MODE 2: fp32 * scale row-major (+batch stride on C)
// MODE 3: fp32 + bias row-major (final output)
template<int MODE>
__global__ void __launch_bounds__(256, 2) gemm_bf16x3(
    const __nv_bfloat16* __restrict__ Ah, const __nv_bfloat16* __restrict__ Al,
    const __nv_bfloat16* __restrict__ Bh, const __nv_bfloat16* __restrict__ Bl,
    int lda, int ldb, int K,
    long long sAz, long long sBz, long long sCz,
    const float* __restrict__ bias, float scale,
    __nv_bfloat16* __restrict__ outH, __nv_bfloat16* __restrict__ outL,
    float* __restrict__ outF, int ldc)
{
    extern __shared__ __align__(1024) char smem_raw[];
    const u32 sb0 = smem_u32(smem_raw);
    const u32 sb  = (sb0 + 1023u) & ~1023u;
    char* smem_ptr = smem_raw + (sb - sb0);

    const int tid  = threadIdx.x;
    const int lane = tid & 31, wid = tid >> 5;
    const int wm = wid & 1, wn = wid >> 1;          // 2 x 4 warp grid
    const int m0 = blockIdx.x * 128, n0 = blockIdx.y * 128;
    const long long z = blockIdx.z;
    Ah += z * sAz; Al += z * sAz; Bh += z * sBz; Bl += z * sBz;

    float acc[4][4][4];
    #pragma unroll
    for (int i = 0; i < 4; ++i)
        #pragma unroll
        for (int j = 0; j < 4; ++j)
            #pragma unroll
            for (int e = 0; e < 4; ++e) acc[i][j][e] = 0.f;

    // ---- cp.async loader: thread t -> row t/2, 2x16B chunks at (t&1)*2 ----
    const int lr  = tid >> 1;
    const int lc0 = (tid & 1) * 2;
    const __nv_bfloat16* gAh = Ah + (size_t)(m0 + lr) * lda + lc0 * 8;
    const __nv_bfloat16* gAl = Al + (size_t)(m0 + lr) * lda + lc0 * 8;
    const __nv_bfloat16* gBh = Bh + (size_t)(n0 + lr) * ldb + lc0 * 8;
    const __nv_bfloat16* gBl = Bl + (size_t)(n0 + lr) * ldb + lc0 * 8;

    auto load_stage = [&](int s, int k0) {
        const u32 b = sb + (u32)s * ST_BYTES;
        #pragma unroll
        for (int j = 0; j < 2; ++j) {
            const u32 dst = b + swz64(lr, lc0 + j);
            cpa16(dst,           gAh + k0 + j * 8);
            cpa16(dst + 8192u,   gAl + k0 + j * 8);
            cpa16(dst + 16384u,  gBh + k0 + j * 8);
            cpa16(dst + 24576u,  gBl + k0 + j * 8);
        }
        CP_COMMIT();
    };

    const int nch = K >> 5;
    load_stage(0, 0);
    load_stage(1, 32);   // all our K >= 128, so nch >= 4 always

    const int rA = lane & 15, cA = lane >> 4;          // ldmatrix x4 lane map (A)
    const int rB = lane & 7,  cB = (lane >> 3) & 1;    // ldmatrix x2 lane map (B)

    // loop-invariant swizzled offsets (A: +am*1024 per 16 rows; B: +bn*512 per 8 rows)
    const u32 offA0 = swz64(wm * 64 + rA, cA);
    const u32 offA1 = swz64(wm * 64 + rA, 2 + cA);
    const u32 offB0 = swz64(wn * 32 + rB, cB);
    const u32 offB1 = swz64(wn * 32 + rB, 2 + cB);

    int sc = 0;          // stage of chunk c
    for (int c = 0; c < nch; ++c) {
        if (c + 1 < nch) { CP_WAIT(1); } else { CP_WAIT(0); }
        __syncthreads();   // data visibility + all warps done reading stage being overwritten

        // prefetch chunk c+2 into the stage that chunk c-1 just finished with
        if (c + 2 < nch) {
            int sl = sc + 2; if (sl >= NSTAGE) sl -= NSTAGE;
            load_stage(sl, (c + 2) * 32);
        }

        const u32 base = sb + (u32)sc * ST_BYTES;
        #pragma unroll
        for (int ks = 0; ks < 2; ++ks) {
            const u32 aoff = base + (ks ? offA1 : offA0);
            const u32 boff = base + 16384u + (ks ? offB1 : offB0);

            // resident operands: B-hi (8 regs) + A-hi (16) + A-lo (16)
            u32 bh[4][2];
            #pragma unroll
            for (int bn = 0; bn < 4; ++bn)
                LDSM2(bh[bn][0], bh[bn][1], boff + (u32)bn * 512u);
            u32 ah[4][4], al[4][4];
            #pragma unroll
            for (int am = 0; am < 4; ++am)
                LDSM4(ah[am][0], ah[am][1], ah[am][2], ah[am][3],
                      aoff + (u32)am * 1024u);
            #pragma unroll
            for (int am = 0; am < 4; ++am)
                LDSM4(al[am][0], al[am][1], al[am][2], al[am][3],
                      aoff + 8192u + (u32)am * 1024u);

            // combo 1: Ah x Bh  (16 independent MMAs)
            #pragma unroll
            for (int am = 0; am < 4; ++am)
                #pragma unroll
                for (int bn = 0; bn < 4; ++bn)
                    mma16816(acc[am][bn], ah[am], bh[bn]);

            // combo 2: Al x Bh  (acc reuse distance = 16 MMAs)
            #pragma unroll
            for (int am = 0; am < 4; ++am)
                #pragma unroll
                for (int bn = 0; bn < 4; ++bn)
                    mma16816(acc[am][bn], al[am], bh[bn]);

            // combo 3: Ah x Bl  (B-lo loaded late; al dead -> regs recycled)
            u32 bl[4][2];
            #pragma unroll
            for (int bn = 0; bn < 4; ++bn)
                LDSM2(bl[bn][0], bl[bn][1], boff + 8192u + (u32)bn * 512u);
            #pragma unroll
            for (int am = 0; am < 4; ++am)
                #pragma unroll
                for (int bn = 0; bn < 4; ++bn)
                    mma16816(acc[am][bn], ah[am], bl[bn]);
        }
        if (++sc >= NSTAGE) sc -= NSTAGE;
    }

    // ======================= epilogue =======================
    const int q = lane >> 2, tq = lane & 3;

    if constexpr (MODE == 1) {
        __syncthreads();   // all warps done with stage smem before T-buffer overwrite
        // transpose 128x128 tile through smem (u32 = packed hi|lo), stride 132
        u32* T = reinterpret_cast<u32*>(smem_ptr);
        #pragma unroll
        for (int am = 0; am < 4; ++am)
            #pragma unroll
            for (int bn = 0; bn < 4; ++bn)
                #pragma unroll
                for (int e = 0; e < 4; ++e) {
                    const int ml = wm * 64 + am * 16 + q + (e >> 1) * 8;
                    const int nl = wn * 32 + bn * 8 + 2 * tq + (e & 1);
                    const float v = acc[am][bn][e] + bias[n0 + nl];
                    const __nv_bfloat16 h = __float2bfloat16(v);
                    const __nv_bfloat16 l = __float2bfloat16(v - __bfloat162float(h));
                    T[nl * 132 + ml] = ((u32)bf_bits(l) << 16) | (u32)bf_bits(h);
                }
        __syncthreads();
        const int d  = tid >> 1;
        const int mh = (tid & 1) * 64;
        const int b  = m0 >> 11;
        const size_t idx = ((size_t)b * CC + (n0 + d)) * TT + (m0 & 2047) + mh;
        #pragma unroll
        for (int i = 0; i < 64; i += 8) {
            u32 hw[4], lw[4];
            #pragma unroll
            for (int p = 0; p < 4; ++p) {
                const u32 t0 = T[d * 132 + mh + i + 2 * p];
                const u32 t1 = T[d * 132 + mh + i + 2 * p + 1];
                hw[p] = (t0 & 0xffffu) | (t1 << 16);
                lw[p] = (t0 >> 16)     | (t1 & 0xffff0000u);
            }
            *reinterpret_cast<uint4*>(outH + idx + i) = make_uint4(hw[0], hw[1], hw[2], hw[3]);
            *reinterpret_cast<uint4*>(outL + idx + i) = make_uint4(lw[0], lw[1], lw[2], lw[3]);
        }
        return;
    } else {

    if (MODE == 0) { outH += z * sCz; outL += z * sCz; }
    else           { outF += z * sCz; }

    #pragma unroll
    for (int am = 0; am < 4; ++am)
        #pragma unroll
        for (int e2 = 0; e2 < 2; ++e2) {
            const int gm = m0 + wm * 64 + am * 16 + q + e2 * 8;
            #pragma unroll
            for (int bn = 0; bn < 4; ++bn) {
                const int gn = n0 + wn * 32 + bn * 8 + 2 * tq;
                float v0 = acc[am][bn][e2 * 2 + 0];
                float v1 = acc[am][bn][e2 * 2 + 1];
                if (MODE == 0) {
                    if (bias) { v0 += bias[gn]; v1 += bias[gn + 1]; }
                    const __nv_bfloat16 h0 = __float2bfloat16(v0), h1 = __float2bfloat16(v1);
                    const __nv_bfloat16 l0 = __float2bfloat16(v0 - __bfloat162float(h0));
                    const __nv_bfloat16 l1 = __float2bfloat16(v1 - __bfloat162float(h1));
                    *reinterpret_cast<u32*>(outH + (size_t)gm * ldc + gn) = pack_bf2(h0, h1);
                    *reinterpret_cast<u32*>(outL + (size_t)gm * ldc + gn) = pack_bf2(l0, l1);
                } else if (MODE == 2) {
                    float2 val; val.x = v0 * scale; val.y = v1 * scale;
                    *reinterpret_cast<float2*>(outF + (size_t)gm * ldc + gn) = val;
                } else {
                    float2 val; val.x = v0 + bias[gn]; val.y = v1 + bias[gn + 1];
                    *reinterpret_cast<float2*>(outF + (size_t)gm * ldc + gn) = val;
                }
            }
        }
    }
}

// ======================= split fp32 -> bf16 hi/lo =======================
__global__ void __launch_bounds__(256) split_kernel(
    const float* __restrict__ x, __nv_bfloat16* __restrict__ h,
    __nv_bfloat16* __restrict__ l, int n4)
{
    int i = blockIdx.x * 256 + threadIdx.x;
    if (i >= n4) return;
    float4 v = reinterpret_cast<const float4*>(x)[i];
    float vv[4] = { v.x, v.y, v.z, v.w };
    __nv_bfloat16 hh[4], ll[4];
    #pragma unroll
    for (int c = 0; c < 4; ++c) {
        hh[c] = __float2bfloat16(vv[c]);
        ll[c] = __float2bfloat16(vv[c] - __bfloat162float(hh[c]));
    }
    *reinterpret_cast<uint2*>(h + 4*(size_t)i) = make_uint2(pack_bf2(hh[0],hh[1]), pack_bf2(hh[2],hh[3]));
    *reinterpret_cast<uint2*>(l + 4*(size_t)i) = make_uint2(pack_bf2(ll[0],ll[1]), pack_bf2(ll[2],ll[3]));
}

// batched weight split: 4 matrices of CC*CC, selected by blockIdx.y
__global__ void __launch_bounds__(256) split_w4_kernel(
    const float* __restrict__ w0, const float* __restrict__ w1,
    const float* __restrict__ w2, const float* __restrict__ w3,
    __nv_bfloat16* __restrict__ h, __nv_bfloat16* __restrict__ l)
{
    const int mat = blockIdx.y;
    const float* src = (mat == 0) ? w0 : (mat == 1) ? w1 : (mat == 2) ? w2 : w3;
    const size_t off = (size_t)mat * CC * CC;
    int i = blockIdx.x * 256 + threadIdx.x;           // i indexes float4
    float4 v = reinterpret_cast<const float4*>(src)[i];
    float vv[4] = { v.x, v.y, v.z, v.w };
    __nv_bfloat16 hh[4], ll[4];
    #pragma unroll
    for (int c = 0; c < 4; ++c) {
        hh[c] = __float2bfloat16(vv[c]);
        ll[c] = __float2bfloat16(vv[c] - __bfloat162float(hh[c]));
    }
    *reinterpret_cast<uint2*>(h + off + 4*(size_t)i) = make_uint2(pack_bf2(hh[0],hh[1]), pack_bf2(hh[2],hh[3]));
    *reinterpret_cast<uint2*>(l + off + 4*(size_t)i) = make_uint2(pack_bf2(ll[0],ll[1]), pack_bf2(ll[2],ll[3]));
}

// ======================= softmax + split =======================
__global__ void __launch_bounds__(256) softmax_split_kernel(
    const float* __restrict__ S, __nv_bfloat16* __restrict__ Ph, __nv_bfloat16* __restrict__ Pl)
{
    __shared__ float red[8];
    __shared__ float sM, sInv;
    const size_t row = blockIdx.x;
    const float4* src = reinterpret_cast<const float4*>(S + row * TT);
    const int t = threadIdx.x, w = t >> 5, ln = t & 31;

    float4 a = src[t], b2 = src[t + 256];
    float mx = fmaxf(fmaxf(fmaxf(a.x, a.y), fmaxf(a.z, a.w)),
                     fmaxf(fmaxf(b2.x, b2.y), fmaxf(b2.z, b2.w)));
    #pragma unroll
    for (int o = 16; o; o >>= 1) mx = fmaxf(mx, __shfl_xor_sync(0xffffffffu, mx, o));
    if (ln == 0) red[w] = mx;
    __syncthreads();
    if (t == 0) {
        float m = red[0];
        #pragma unroll
        for (int i = 1; i < 8; ++i) m = fmaxf(m, red[i]);
        sM = m;
    }
    __syncthreads();
    const float M = sM;

    float e[8];
    e[0] = __expf(a.x - M);  e[1] = __expf(a.y - M);
    e[2] = __expf(a.z - M);  e[3] = __expf(a.w - M);
    e[4] = __expf(b2.x - M); e[5] = __expf(b2.y - M);
    e[6] = __expf(b2.z - M); e[7] = __expf(b2.w - M);
    float sm = e[0]+e[1]+e[2]+e[3]+e[4]+e[5]+e[6]+e[7];
    #pragma unroll
    for (int o = 16; o; o >>= 1) sm += __shfl_xor_sync(0xffffffffu, sm, o);
    __syncthreads();
    if (ln == 0) red[w] = sm;
    __syncthreads();
    if (t == 0) {
        float ssum = 0.f;
        #pragma unroll
        for (int i = 0; i < 8; ++i) ssum += red[i];
        sInv = 1.0f / ssum;
    }
    __syncthreads();
    const float inv = sInv;

    #pragma unroll
    for (int half = 0; half < 2; ++half) {
        __nv_bfloat16 hh[4], ll[4];
        #pragma unroll
        for (int c = 0; c < 4; ++c) {
            float p = e[half*4 + c] * inv;
            hh[c] = __float2bfloat16(p);
            ll[c] = __float2bfloat16(p - __bfloat162float(hh[c]));
        }
        size_t off = row * TT + (size_t)(t + half*256) * 4;
        *reinterpret_cast<uint2*>(Ph + off) = make_uint2(pack_bf2(hh[0],hh[1]), pack_bf2(hh[2],hh[3]));
        *reinterpret_cast<uint2*>(Pl + off) = make_uint2(pack_bf2(ll[0],ll[1]), pack_bf2(ll[2],ll[3]));
    }
}

// ======================= host launch =======================
static void* sym_addr(const void* s) {
    void* p = nullptr;
    cudaGetSymbolAddress(&p, s);
    return p;
}

extern "C" void kernel_launch(void* const* d_in, const int* in_sizes, int n_in,
                              void* d_out, int out_size) {
    (void)in_sizes; (void)n_in; (void)out_size;
    const float* x  = (const float*)d_in[0];
    const float* Wq = (const float*)d_in[1];
    const float* bq = (const float*)d_in[2];
    const float* Wk = (const float*)d_in[3];
    const float* bk = (const float*)d_in[4];
    const float* Wv = (const float*)d_in[5];
    const float* bv = (const float*)d_in[6];
    const float* Wo = (const float*)d_in[7];
    const float* bo = (const float*)d_in[8];
    float* out = (float*)d_out;

    __nv_bfloat16* xh  = (__nv_bfloat16*)sym_addr(g_xh);
    __nv_bfloat16* xl  = (__nv_bfloat16*)sym_addr(g_xl);
    __nv_bfloat16* wh  = (__nv_bfloat16*)sym_addr(g_wh);
    __nv_bfloat16* wl  = (__nv_bfloat16*)sym_addr(g_wl);
    __nv_bfloat16* qh  = (__nv_bfloat16*)sym_addr(g_qh);
    __nv_bfloat16* ql  = (__nv_bfloat16*)sym_addr(g_ql);
    __nv_bfloat16* kh  = (__nv_bfloat16*)sym_addr(g_kh);
    __nv_bfloat16* kl  = (__nv_bfloat16*)sym_addr(g_kl);
    __nv_bfloat16* vth = (__nv_bfloat16*)sym_addr(g_vth);
    __nv_bfloat16* vtl = (__nv_bfloat16*)sym_addr(g_vtl);
    float*         sS  = (float*)sym_addr(g_s);
    __nv_bfloat16* ph  = (__nv_bfloat16*)sym_addr(g_ph);
    __nv_bfloat16* pl  = (__nv_bfloat16*)sym_addr(g_pl);
    __nv_bfloat16* ch  = (__nv_bfloat16*)sym_addr(g_ch);
    __nv_bfloat16* cl  = (__nv_bfloat16*)sym_addr(g_cl);

    cudaFuncSetAttribute(gemm_bf16x3<0>, cudaFuncAttributeMaxDynamicSharedMemorySize, SMEM_BYTES);
    cudaFuncSetAttribute(gemm_bf16x3<1>, cudaFuncAttributeMaxDynamicSharedMemorySize, SMEM_BYTES);
    cudaFuncSetAttribute(gemm_bf16x3<2>, cudaFuncAttributeMaxDynamicSharedMemorySize, SMEM_BYTES);
    cudaFuncSetAttribute(gemm_bf16x3<3>, cudaFuncAttributeMaxDynamicSharedMemorySize, SMEM_BYTES);

    // launch 0: split x; launch 1: split 4 weights (batched)
    split_kernel<<<(MROWS*CC/4 + 255)/256, 256>>>(x, xh, xl, MROWS*CC/4);
    dim3 gW(CC*CC/4/256, 4);
    split_w4_kernel<<<gW, 256>>>(Wq, Wk, Wv, Wo, wh, wl);

    dim3 gProj(MROWS/128, CC/128, 1);     // (64, 8, 1)
    // launch 2: Q = x Wq^T + bq
    gemm_bf16x3<0><<<gProj, 256, SMEM_BYTES>>>(xh, xl, wh + 0*(size_t)CC*CC, wl + 0*(size_t)CC*CC,
        CC, CC, CC, 0, 0, 0, bq, 1.f, qh, ql, nullptr, CC);
    // launch 3: K
    gemm_bf16x3<0><<<gProj, 256, SMEM_BYTES>>>(xh, xl, wh + 1*(size_t)CC*CC, wl + 1*(size_t)CC*CC,
        CC, CC, CC, 0, 0, 0, bk, 1.f, kh, kl, nullptr, CC);
    // launch 4: V -> transposed store vt[b][d][s]
    gemm_bf16x3<1><<<gProj, 256, SMEM_BYTES>>>(xh, xl, wh + 2*(size_t)CC*CC, wl + 2*(size_t)CC*CC,
        CC, CC, CC, 0, 0, 0, bv, 1.f, vth, vtl, nullptr, 0);

    // launch 5: scores = Q K^T / 32  (per batch)
    dim3 gScore(TT/128, TT/128, BN);      // (16, 16, 4)
    gemm_bf16x3<2><<<gScore, 256, SMEM_BYTES>>>(qh, ql, kh, kl,
        CC, CC, CC, (long long)TT*CC, (long long)TT*CC, (long long)TT*TT,
        nullptr, 0.03125f, nullptr, nullptr, sS, TT);

    // softmax + split
    softmax_split_kernel<<<MROWS, 256>>>(sS, ph, pl);

    // ctx = P V  (A = P [t][s], B = vt [d][s], per batch)
    dim3 gPV(TT/128, CC/128, BN);         // (16, 8, 4)
    gemm_bf16x3<0><<<gPV, 256, SMEM_BYTES>>>(ph, pl, vth, vtl,
        TT, TT, TT, (long long)TT*TT, (long long)CC*TT, (long long)TT*CC,
        nullptr, 1.f, ch, cl, nullptr, CC);

    // out = ctx Wo^T + bo  (fp32 -> d_out)
    gemm_bf16x3<3><<<gProj, 256, SMEM_BYTES>>>(ch, cl, wh + 3*(size_t)CC*CC, wl + 3*(size_t)CC*CC,
        CC, CC, CC, 0, 0, 0, bo, 1.f, nullptr, nullptr, out, CC);
}

// round 10
// speedup vs baseline: 1.0074x; 1.0074x over previous
#include <cuda_runtime.h>
#include <cuda_bf16.h>
#include <cstdint>
#include <cstddef>

typedef unsigned int u32;

#define BN 4
#define TT 2048
#define CC 1024
#define MROWS (BN*TT)   // 8192

// ======================= device scratch (no allocs allowed) =======================
__device__ __align__(256) __nv_bfloat16 g_xh[MROWS*CC];
__device__ __align__(256) __nv_bfloat16 g_xl[MROWS*CC];
__device__ __align__(256) __nv_bfloat16 g_wh[4*CC*CC];
__device__ __align__(256) __nv_bfloat16 g_wl[4*CC*CC];
__device__ __align__(256) __nv_bfloat16 g_qh[MROWS*CC];
__device__ __align__(256) __nv_bfloat16 g_ql[MROWS*CC];
__device__ __align__(256) __nv_bfloat16 g_kh[MROWS*CC];
__device__ __align__(256) __nv_bfloat16 g_kl[MROWS*CC];
__device__ __align__(256) __nv_bfloat16 g_vth[MROWS*CC];  // V^T: [b][d][s]
__device__ __align__(256) __nv_bfloat16 g_vtl[MROWS*CC];
__device__ __align__(256) float         g_s [(size_t)BN*TT*TT];
__device__ __align__(256) __nv_bfloat16 g_ph[(size_t)BN*TT*TT];
__device__ __align__(256) __nv_bfloat16 g_pl[(size_t)BN*TT*TT];
__device__ __align__(256) __nv_bfloat16 g_ch[MROWS*CC];
__device__ __align__(256) __nv_bfloat16 g_cl[MROWS*CC];

// ======================= PTX helpers (sm_100 baseline, NO 'a' features) =======================
__device__ __forceinline__ u32 smem_u32(const void* p) {
    u32 a;
    asm("{ .reg .u64 t; cvta.to.shared.u64 t, %1; cvt.u32.u64 %0, t; }" : "=r"(a) : "l"(p));
    return a;
}
__device__ __forceinline__ void cpa16(u32 dst, const void* src) {
    asm volatile("cp.async.cg.shared.global [%0], [%1], 16;" :: "r"(dst), "l"(src) : "memory");
}
#define CP_COMMIT() asm volatile("cp.async.commit_group;" ::: "memory")
#define CP_WAIT(n)  asm volatile("cp.async.wait_group %0;" :: "n"(n) : "memory")

#define LDSM4(d0,d1,d2,d3,a) \
    asm volatile("ldmatrix.sync.aligned.m8n8.x4.shared.b16 {%0,%1,%2,%3}, [%4];" \
                 : "=r"(d0),"=r"(d1),"=r"(d2),"=r"(d3) : "r"(a))
#define LDSM2(d0,d1,a) \
    asm volatile("ldmatrix.sync.aligned.m8n8.x2.shared.b16 {%0,%1}, [%2];" \
                 : "=r"(d0),"=r"(d1) : "r"(a))

__device__ __forceinline__ void mma16816(float* c, const u32* a, const u32* b) {
    asm volatile(
        "mma.sync.aligned.m16n8k16.row.col.f32.bf16.bf16.f32 "
        "{%0,%1,%2,%3}, {%4,%5,%6,%7}, {%8,%9}, {%0,%1,%2,%3};"
        : "+f"(c[0]), "+f"(c[1]), "+f"(c[2]), "+f"(c[3])
        : "r"(a[0]), "r"(a[1]), "r"(a[2]), "r"(a[3]), "r"(b[0]), "r"(b[1]));
}

__device__ __forceinline__ u32 pack_bf2(__nv_bfloat16 a, __nv_bfloat16 b) {
    __nv_bfloat162 t = __halves2bfloat162(a, b);
    return *reinterpret_cast<u32*>(&t);
}
__device__ __forceinline__ unsigned short bf_bits(__nv_bfloat16 h) {
    return *reinterpret_cast<unsigned short*>(&h);
}

// 64B-row swizzle: row*64 + ((c16 ^ ((row>>1)&3)) << 4); bijective over the 8
// 16B slots per 128B phase; additive in row steps of 8/16 -> LDSM addresses
// collapse to base + constant.
__device__ __forceinline__ u32 swz64(int row, int c16) {
    return (u32)row * 64u + (u32)((c16 ^ ((row >> 1) & 3)) << 4);
}

// ======================= GEMM kernel =======================
// Tile 128x128, K-chunk 32. Stage: Ah(8K) Al(8K) Bh(8K) Bl(8K) = 32KB; 3 stages.
// 2 CTAs/SM (regs capped at 128, smem 97KB/CTA).
#define ST_BYTES   32768u
#define NSTAGE     3
#define SMEM_BYTES (1024 + NSTAGE*32768)   // 99328

// MODE 0: split bf16 hi/lo row-major (+optional bias, +batch stride on C)
// MODE 1: V-projection: bias then transposed split store into vt[b][d][s]
// MODE 2: fp32 * scale row-major (+batch stride on C)
// MODE 3: fp32 + bias row-major (final output)
template<int MODE>
__global__ void __launch_bounds__(256, 2) gemm_bf16x3(
    const __nv_bfloat16* __restrict__ Ah, const __nv_bfloat16* __restrict__ Al,
    const __nv_bfloat16* __restrict__ Bh, const __nv_bfloat16* __restrict__ Bl,
    int lda, int ldb, int K,
    long long sAz, long long sBz, long long sCz,
    const float* __restrict__ bias, float scale,
    __nv_bfloat16* __restrict__ outH, __nv_bfloat16* __restrict__ outL,
    float* __restrict__ outF, int ldc)
{
    extern __shared__ __align__(1024) char smem_raw[];
    const u32 sb0 = smem_u32(smem_raw);
    const u32 sb  = (sb0 + 1023u) & ~1023u;
    char* smem_ptr = smem_raw + (sb - sb0);

    const int tid  = threadIdx.x;
    const int lane = tid & 31, wid = tid >> 5;
    const int wm = wid & 1, wn = wid >> 1;          // 2 x 4 warp grid
    const int m0 = blockIdx.x * 128, n0 = blockIdx.y * 128;
    const long long z = blockIdx.z;
    Ah += z * sAz; Al += z * sAz; Bh += z * sBz; Bl += z * sBz;

    float acc[4][4][4];
    #pragma unroll
    for (int i = 0; i < 4; ++i)
        #pragma unroll
        for (int j = 0; j < 4; ++j)
            #pragma unroll
            for (int e = 0; e < 4; ++e) acc[i][j][e] = 0.f;

    // ---- cp.async loader: thread t -> row t/2, 2x16B chunks at (t&1)*2 ----
    const int lr  = tid >> 1;
    const int lc0 = (tid & 1) * 2;
    const __nv_bfloat16* gAh = Ah + (size_t)(m0 + lr) * lda + lc0 * 8;
    const __nv_bfloat16* gAl = Al + (size_t)(m0 + lr) * lda + lc0 * 8;
    const __nv_bfloat16* gBh = Bh + (size_t)(n0 + lr) * ldb + lc0 * 8;
    const __nv_bfloat16* gBl = Bl + (size_t)(n0 + lr) * ldb + lc0 * 8;

    auto load_stage = [&](int s, int k0) {
        const u32 b = sb + (u32)s * ST_BYTES;
        #pragma unroll
        for (int j = 0; j < 2; ++j) {
            const u32 dst = b + swz64(lr, lc0 + j);
            cpa16(dst,           gAh + k0 + j * 8);
            cpa16(dst + 8192u,   gAl + k0 + j * 8);
            cpa16(dst + 16384u,  gBh + k0 + j * 8);
            cpa16(dst + 24576u,  gBl + k0 + j * 8);
        }
        CP_COMMIT();
    };

    const int nch = K >> 5;
    load_stage(0, 0);
    load_stage(1, 32);   // all our K >= 128, so nch >= 4 always

    const int rA = lane & 15, cA = lane >> 4;          // ldmatrix x4 lane map (A)
    const int rB = lane & 7,  cB = (lane >> 3) & 1;    // ldmatrix x2 lane map (B)

    // loop-invariant swizzled offsets (A: +am*1024 per 16 rows; B: +bn*512 per 8 rows)
    const u32 offA0 = swz64(wm * 64 + rA, cA);
    const u32 offA1 = swz64(wm * 64 + rA, 2 + cA);
    const u32 offB0 = swz64(wn * 32 + rB, cB);
    const u32 offB1 = swz64(wn * 32 + rB, 2 + cB);

    // warp-parity k-slice stagger: even warps do ks 0,1; odd warps ks 1,0.
    // Breaks the CTA-wide LDSM/MMA phase lockstep so the smem crossbar and
    // tensor pipe run concurrently instead of alternating.
    const int kpar = wid & 1;

    int sc = 0;          // stage of chunk c
    for (int c = 0; c < nch; ++c) {
        if (c + 1 < nch) { CP_WAIT(1); } else { CP_WAIT(0); }
        __syncthreads();   // data visibility + all warps done reading stage being overwritten

        // prefetch chunk c+2 into the stage that chunk c-1 just finished with
        if (c + 2 < nch) {
            int sl = sc + 2; if (sl >= NSTAGE) sl -= NSTAGE;
            load_stage(sl, (c + 2) * 32);
        }

        const u32 base = sb + (u32)sc * ST_BYTES;
        #pragma unroll
        for (int ksi = 0; ksi < 2; ++ksi) {
            const int ks = ksi ^ kpar;
            const u32 aoff = base + (ks ? offA1 : offA0);
            const u32 boff = base + 16384u + (ks ? offB1 : offB0);

            // resident B: hi and lo for all 4 bn (16 regs)
            u32 bh[4][2], bl[4][2];
            #pragma unroll
            for (int bn = 0; bn < 4; ++bn)
                LDSM2(bh[bn][0], bh[bn][1], boff + (u32)bn * 512u);
            #pragma unroll
            for (int bn = 0; bn < 4; ++bn)
                LDSM2(bl[bn][0], bl[bn][1], boff + 8192u + (u32)bn * 512u);

            // stream A: per am load hi+lo (8 regs), fire 12 MMAs
            #pragma unroll
            for (int am = 0; am < 4; ++am) {
                u32 ah[4], al[4];
                LDSM4(ah[0], ah[1], ah[2], ah[3], aoff + (u32)am * 1024u);
                LDSM4(al[0], al[1], al[2], al[3], aoff + 8192u + (u32)am * 1024u);
                #pragma unroll
                for (int bn = 0; bn < 4; ++bn)
                    mma16816(acc[am][bn], ah, bh[bn]);
                #pragma unroll
                for (int bn = 0; bn < 4; ++bn)
                    mma16816(acc[am][bn], al, bh[bn]);
                #pragma unroll
                for (int bn = 0; bn < 4; ++bn)
                    mma16816(acc[am][bn], ah, bl[bn]);
            }
        }
        if (++sc >= NSTAGE) sc -= NSTAGE;
    }

    // ======================= epilogue =======================
    const int q = lane >> 2, tq = lane & 3;

    if constexpr (MODE == 1) {
        __syncthreads();   // all warps done with stage smem before T-buffer overwrite
        // transpose 128x128 tile through smem (u32 = packed hi|lo), stride 132
        u32* T = reinterpret_cast<u32*>(smem_ptr);
        #pragma unroll
        for (int am = 0; am < 4; ++am)
            #pragma unroll
            for (int bn = 0; bn < 4; ++bn)
                #pragma unroll
                for (int e = 0; e < 4; ++e) {
                    const int ml = wm * 64 + am * 16 + q + (e >> 1) * 8;
                    const int nl = wn * 32 + bn * 8 + 2 * tq + (e & 1);
                    const float v = acc[am][bn][e] + bias[n0 + nl];
                    const __nv_bfloat16 h = __float2bfloat16(v);
                    const __nv_bfloat16 l = __float2bfloat16(v - __bfloat162float(h));
                    T[nl * 132 + ml] = ((u32)bf_bits(l) << 16) | (u32)bf_bits(h);
                }
        __syncthreads();
        const int d  = tid >> 1;
        const int mh = (tid & 1) * 64;
        const int b  = m0 >> 11;
        const size_t idx = ((size_t)b * CC + (n0 + d)) * TT + (m0 & 2047) + mh;
        #pragma unroll
        for (int i = 0; i < 64; i += 8) {
            u32 hw[4], lw[4];
            #pragma unroll
            for (int p = 0; p < 4; ++p) {
                const u32 t0 = T[d * 132 + mh + i + 2 * p];
                const u32 t1 = T[d * 132 + mh + i + 2 * p + 1];
                hw[p] = (t0 & 0xffffu) | (t1 << 16);
                lw[p] = (t0 >> 16)     | (t1 & 0xffff0000u);
            }
            *reinterpret_cast<uint4*>(outH + idx + i) = make_uint4(hw[0], hw[1], hw[2], hw[3]);
            *reinterpret_cast<uint4*>(outL + idx + i) = make_uint4(lw[0], lw[1], lw[2], lw[3]);
        }
        return;
    } else {

    if (MODE == 0) { outH += z * sCz; outL += z * sCz; }
    else           { outF += z * sCz; }

    #pragma unroll
    for (int am = 0; am < 4; ++am)
        #pragma unroll
        for (int e2 = 0; e2 < 2; ++e2) {
            const int gm = m0 + wm * 64 + am * 16 + q + e2 * 8;
            #pragma unroll
            for (int bn = 0; bn < 4; ++bn) {
                const int gn = n0 + wn * 32 + bn * 8 + 2 * tq;
                float v0 = acc[am][bn][e2 * 2 + 0];
                float v1 = acc[am][bn][e2 * 2 + 1];
                if (MODE == 0) {
                    if (bias) { v0 += bias[gn]; v1 += bias[gn + 1]; }
                    const __nv_bfloat16 h0 = __float2bfloat16(v0), h1 = __float2bfloat16(v1);
                    const __nv_bfloat16 l0 = __float2bfloat16(v0 - __bfloat162float(h0));
                    const __nv_bfloat16 l1 = __float2bfloat16(v1 - __bfloat162float(h1));
                    *reinterpret_cast<u32*>(outH + (size_t)gm * ldc + gn) = pack_bf2(h0, h1);
                    *reinterpret_cast<u32*>(outL + (size_t)gm * ldc + gn) = pack_bf2(l0, l1);
                } else if (MODE == 2) {
                    float2 val; val.x = v0 * scale; val.y = v1 * scale;
                    *reinterpret_cast<float2*>(outF + (size_t)gm * ldc + gn) = val;
                } else {
                    float2 val; val.x = v0 + bias[gn]; val.y = v1 + bias[gn + 1];
                    *reinterpret_cast<float2*>(outF + (size_t)gm * ldc + gn) = val;
                }
            }
        }
    }
}

// ======================= split fp32 -> bf16 hi/lo =======================
__global__ void __launch_bounds__(256) split_kernel(
    const float* __restrict__ x, __nv_bfloat16* __restrict__ h,
    __nv_bfloat16* __restrict__ l, int n4)
{
    int i = blockIdx.x * 256 + threadIdx.x;
    if (i >= n4) return;
    float4 v = reinterpret_cast<const float4*>(x)[i];
    float vv[4] = { v.x, v.y, v.z, v.w };
    __nv_bfloat16 hh[4], ll[4];
    #pragma unroll
    for (int c = 0; c < 4; ++c) {
        hh[c] = __float2bfloat16(vv[c]);
        ll[c] = __float2bfloat16(vv[c] - __bfloat162float(hh[c]));
    }
    *reinterpret_cast<uint2*>(h + 4*(size_t)i) = make_uint2(pack_bf2(hh[0],hh[1]), pack_bf2(hh[2],hh[3]));
    *reinterpret_cast<uint2*>(l + 4*(size_t)i) = make_uint2(pack_bf2(ll[0],ll[1]), pack_bf2(ll[2],ll[3]));
}

// batched weight split: 4 matrices of CC*CC, selected by blockIdx.y
__global__ void __launch_bounds__(256) split_w4_kernel(
    const float* __restrict__ w0, const float* __restrict__ w1,
    const float* __restrict__ w2, const float* __restrict__ w3,
    __nv_bfloat16* __restrict__ h, __nv_bfloat16* __restrict__ l)
{
    const int mat = blockIdx.y;
    const float* src = (mat == 0) ? w0 : (mat == 1) ? w1 : (mat == 2) ? w2 : w3;
    const size_t off = (size_t)mat * CC * CC;
    int i = blockIdx.x * 256 + threadIdx.x;           // i indexes float4
    float4 v = reinterpret_cast<const float4*>(src)[i];
    float vv[4] = { v.x, v.y, v.z, v.w };
    __nv_bfloat16 hh[4], ll[4];
    #pragma unroll
    for (int c = 0; c < 4; ++c) {
        hh[c] = __float2bfloat16(vv[c]);
        ll[c] = __float2bfloat16(vv[c] - __bfloat162float(hh[c]));
    }
    *reinterpret_cast<uint2*>(h + off + 4*(size_t)i) = make_uint2(pack_bf2(hh[0],hh[1]), pack_bf2(hh[2],hh[3]));
    *reinterpret_cast<uint2*>(l + off + 4*(size_t)i) = make_uint2(pack_bf2(ll[0],ll[1]), pack_bf2(ll[2],ll[3]));
}

// ======================= softmax + split =======================
__global__ void __launch_bounds__(256) softmax_split_kernel(
    const float* __restrict__ S, __nv_bfloat16* __restrict__ Ph, __nv_bfloat16* __restrict__ Pl)
{
    __shared__ float red[8];
    __shared__ float sM, sInv;
    const size_t row = blockIdx.x;
    const float4* src = reinterpret_cast<const float4*>(S + row * TT);
    const int t = threadIdx.x, w = t >> 5, ln = t & 31;

    float4 a = src[t], b2 = src[t + 256];
    float mx = fmaxf(fmaxf(fmaxf(a.x, a.y), fmaxf(a.z, a.w)),
                     fmaxf(fmaxf(b2.x, b2.y), fmaxf(b2.z, b2.w)));
    #pragma unroll
    for (int o = 16; o; o >>= 1) mx = fmaxf(mx, __shfl_xor_sync(0xffffffffu, mx, o));
    if (ln == 0) red[w] = mx;
    __syncthreads();
    if (t == 0) {
        float m = red[0];
        #pragma unroll
        for (int i = 1; i < 8; ++i) m = fmaxf(m, red[i]);
        sM = m;
    }
    __syncthreads();
    const float M = sM;

    float e[8];
    e[0] = __expf(a.x - M);  e[1] = __expf(a.y - M);
    e[2] = __expf(a.z - M);  e[3] = __expf(a.w - M);
    e[4] = __expf(b2.x - M); e[5] = __expf(b2.y - M);
    e[6] = __expf(b2.z - M); e[7] = __expf(b2.w - M);
    float sm = e[0]+e[1]+e[2]+e[3]+e[4]+e[5]+e[6]+e[7];
    #pragma unroll
    for (int o = 16; o; o >>= 1) sm += __shfl_xor_sync(0xffffffffu, sm, o);
    __syncthreads();
    if (ln == 0) red[w] = sm;
    __syncthreads();
    if (t == 0) {
        float ssum = 0.f;
        #pragma unroll
        for (int i = 0; i < 8; ++i) ssum += red[i];
        sInv = 1.0f / ssum;
    }
    __syncthreads();
    const float inv = sInv;

    #pragma unroll
    for (int half = 0; half < 2; ++half) {
        __nv_bfloat16 hh[4], ll[4];
        #pragma unroll
        for (int c = 0; c < 4; ++c) {
            float p = e[half*4 + c] * inv;
            hh[c] = __float2bfloat16(p);
            ll[c] = __float2bfloat16(p - __bfloat162float(hh[c]));
        }
        size_t off = row * TT + (size_t)(t + half*256) * 4;
        *reinterpret_cast<uint2*>(Ph + off) = make_uint2(pack_bf2(hh[0],hh[1]), pack_bf2(hh[2],hh[3]));
        *reinterpret_cast<uint2*>(Pl + off) = make_uint2(pack_bf2(ll[0],ll[1]), pack_bf2(ll[2],ll[3]));
    }
}

// ======================= host launch =======================
static void* sym_addr(const void* s) {
    void* p = nullptr;
    cudaGetSymbolAddress(&p, s);
    return p;
}

extern "C" void kernel_launch(void* const* d_in, const int* in_sizes, int n_in,
                              void* d_out, int out_size) {
    (void)in_sizes; (void)n_in; (void)out_size;
    const float* x  = (const float*)d_in[0];
    const float* Wq = (const float*)d_in[1];
    const float* bq = (const float*)d_in[2];
    const float* Wk = (const float*)d_in[3];
    const float* bk = (const float*)d_in[4];
    const float* Wv = (const float*)d_in[5];
    const float* bv = (const float*)d_in[6];
    const float* Wo = (const float*)d_in[7];
    const float* bo = (const float*)d_in[8];
    float* out = (float*)d_out;

    __nv_bfloat16* xh  = (__nv_bfloat16*)sym_addr(g_xh);
    __nv_bfloat16* xl  = (__nv_bfloat16*)sym_addr(g_xl);
    __nv_bfloat16* wh  = (__nv_bfloat16*)sym_addr(g_wh);
    __nv_bfloat16* wl  = (__nv_bfloat16*)sym_addr(g_wl);
    __nv_bfloat16* qh  = (__nv_bfloat16*)sym_addr(g_qh);
    __nv_bfloat16* ql  = (__nv_bfloat16*)sym_addr(g_ql);
    __nv_bfloat16* kh  = (__nv_bfloat16*)sym_addr(g_kh);
    __nv_bfloat16* kl  = (__nv_bfloat16*)sym_addr(g_kl);
    __nv_bfloat16* vth = (__nv_bfloat16*)sym_addr(g_vth);
    __nv_bfloat16* vtl = (__nv_bfloat16*)sym_addr(g_vtl);
    float*         sS  = (float*)sym_addr(g_s);
    __nv_bfloat16* ph  = (__nv_bfloat16*)sym_addr(g_ph);
    __nv_bfloat16* pl  = (__nv_bfloat16*)sym_addr(g_pl);
    __nv_bfloat16* ch  = (__nv_bfloat16*)sym_addr(g_ch);
    __nv_bfloat16* cl  = (__nv_bfloat16*)sym_addr(g_cl);

    cudaFuncSetAttribute(gemm_bf16x3<0>, cudaFuncAttributeMaxDynamicSharedMemorySize, SMEM_BYTES);
    cudaFuncSetAttribute(gemm_bf16x3<1>, cudaFuncAttributeMaxDynamicSharedMemorySize, SMEM_BYTES);
    cudaFuncSetAttribute(gemm_bf16x3<2>, cudaFuncAttributeMaxDynamicSharedMemorySize, SMEM_BYTES);
    cudaFuncSetAttribute(gemm_bf16x3<3>, cudaFuncAttributeMaxDynamicSharedMemorySize, SMEM_BYTES);

    // launch 0: split x; launch 1: split 4 weights (batched)
    split_kernel<<<(MROWS*CC/4 + 255)/256, 256>>>(x, xh, xl, MROWS*CC/4);
    dim3 gW(CC*CC/4/256, 4);
    split_w4_kernel<<<gW, 256>>>(Wq, Wk, Wv, Wo, wh, wl);

    dim3 gProj(MROWS/128, CC/128, 1);     // (64, 8, 1)
    // launch 2: Q = x Wq^T + bq
    gemm_bf16x3<0><<<gProj, 256, SMEM_BYTES>>>(xh, xl, wh + 0*(size_t)CC*CC, wl + 0*(size_t)CC*CC,
        CC, CC, CC, 0, 0, 0, bq, 1.f, qh, ql, nullptr, CC);
    // launch 3: K
    gemm_bf16x3<0><<<gProj, 256, SMEM_BYTES>>>(xh, xl, wh + 1*(size_t)CC*CC, wl + 1*(size_t)CC*CC,
        CC, CC, CC, 0, 0, 0, bk, 1.f, kh, kl, nullptr, CC);
    // launch 4: V -> transposed store vt[b][d][s]
    gemm_bf16x3<1><<<gProj, 256, SMEM_BYTES>>>(xh, xl, wh + 2*(size_t)CC*CC, wl + 2*(size_t)CC*CC,
        CC, CC, CC, 0, 0, 0, bv, 1.f, vth, vtl, nullptr, 0);

    // launch 5: scores = Q K^T / 32  (per batch)
    dim3 gScore(TT/128, TT/128, BN);      // (16, 16, 4)
    gemm_bf16x3<2><<<gScore, 256, SMEM_BYTES>>>(qh, ql, kh, kl,
        CC, CC, CC, (long long)TT*CC, (long long)TT*CC, (long long)TT*TT,
        nullptr, 0.03125f, nullptr, nullptr, sS, TT);

    // softmax + split
    softmax_split_kernel<<<MROWS, 256>>>(sS, ph, pl);

    // ctx = P V  (A = P [t][s], B = vt [d][s], per batch)
    dim3 gPV(TT/128, CC/128, BN);         // (16, 8, 4)
    gemm_bf16x3<0><<<gPV, 256, SMEM_BYTES>>>(ph, pl, vth, vtl,
        TT, TT, TT, (long long)TT*TT, (long long)CC*TT, (long long)TT*CC,
        nullptr, 1.f, ch, cl, nullptr, CC);

    // out = ctx Wo^T + bo  (fp32 -> d_out)
    gemm_bf16x3<3><<<gProj, 256, SMEM_BYTES>>>(ch, cl, wh + 3*(size_t)CC*CC, wl + 3*(size_t)CC*CC,
        CC, CC, CC, 0, 0, 0, bo, 1.f, nullptr, nullptr, out, CC);
}

// round 11
// speedup vs baseline: 1.2596x; 1.2504x over previous
#include <cuda_runtime.h>
#include <cstdint>
#include <cstddef>

typedef unsigned int u32;

#define BN 4
#define TT 2048
#define CC 1024
#define MROWS (BN*TT)   // 8192

// ======================= device scratch (fp32, tf32-rounded) =======================
__device__ __align__(256) float g_xr[MROWS*CC];            // 32MB
__device__ __align__(256) float g_wr[4*CC*CC];             // 16MB
__device__ __align__(256) float g_q [MROWS*CC];            // 32MB
__device__ __align__(256) float g_k [MROWS*CC];            // 32MB
__device__ __align__(256) float g_vt[MROWS*CC];            // V^T [b][d][s], 32MB
__device__ __align__(256) float g_s [(size_t)BN*TT*TT];    // 64MB
__device__ __align__(256) float g_p [(size_t)BN*TT*TT];    // 64MB
__device__ __align__(256) float g_c [MROWS*CC];            // 32MB

// ======================= PTX helpers (sm_100 baseline, NO 'a' features) =======================
__device__ __forceinline__ u32 smem_u32(const void* p) {
    u32 a;
    asm("{ .reg .u64 t; cvta.to.shared.u64 t, %1; cvt.u32.u64 %0, t; }" : "=r"(a) : "l"(p));
    return a;
}
__device__ __forceinline__ void cpa16(u32 dst, const void* src) {
    asm volatile("cp.async.cg.shared.global [%0], [%1], 16;" :: "r"(dst), "l"(src) : "memory");
}
#define CP_COMMIT() asm volatile("cp.async.commit_group;" ::: "memory")
#define CP_WAIT(n)  asm volatile("cp.async.wait_group %0;" :: "n"(n) : "memory")

#define LDSM4(d0,d1,d2,d3,a) \
    asm volatile("ldmatrix.sync.aligned.m8n8.x4.shared.b16 {%0,%1,%2,%3}, [%4];" \
                 : "=r"(d0),"=r"(d1),"=r"(d2),"=r"(d3) : "r"(a))
#define LDSM2(d0,d1,a) \
    asm volatile("ldmatrix.sync.aligned.m8n8.x2.shared.b16 {%0,%1}, [%2];" \
                 : "=r"(d0),"=r"(d1) : "r"(a))

// m16n8k8 tf32: A = 4 regs (8x4 fp32 tiles), B = 2 regs, fp32 accum.
__device__ __forceinline__ void mma_tf32(float* c, const u32* a, const u32* b) {
    asm volatile(
        "mma.sync.aligned.m16n8k8.row.col.f32.tf32.tf32.f32 "
        "{%0,%1,%2,%3}, {%4,%5,%6,%7}, {%8,%9}, {%0,%1,%2,%3};"
        : "+f"(c[0]), "+f"(c[1]), "+f"(c[2]), "+f"(c[3])
        : "r"(a[0]), "r"(a[1]), "r"(a[2]), "r"(a[3]), "r"(b[0]), "r"(b[1]));
}

__device__ __forceinline__ u32 tf32r(float f) {
    u32 u; asm("cvt.rna.tf32.f32 %0, %1;" : "=r"(u) : "f"(f)); return u;
}
__device__ __forceinline__ float tf32f(float f) { return __uint_as_float(tf32r(f)); }

// ======================= GEMM kernel =======================
// Tile 128x128, K-chunk 32 (fp32). Stage: A 16KB + B 16KB = 32KB; 3 stages; 2 CTAs/SM.
// fp32 row = 32 floats = 128B -> SW128 swizzle: row*128 + ((c16 ^ (row&7))<<4).
#define ST_BYTES   32768u
#define NSTAGE     3
#define SMEM_BYTES (1024 + NSTAGE*32768)   // 99328

// MODE 0: tf32-rounded fp32 out (+optional bias, +batch stride on C)     [Q,K,ctx]
// MODE 1: V-projection: bias, tf32 round, transposed store into vt[b][d][s]
// MODE 2: fp32 * scale (full precision out)                              [scores]
// MODE 3: fp32 + bias (final output)
template<int MODE>
__global__ void __launch_bounds__(256, 2) gemm_tf32(
    const float* __restrict__ A, const float* __restrict__ B,
    int lda, int ldb, int K,
    long long sAz, long long sBz, long long sCz,
    const float* __restrict__ bias, float scale,
    float* __restrict__ outF, int ldc)
{
    extern __shared__ __align__(1024) char smem_raw[];
    const u32 sb0 = smem_u32(smem_raw);
    const u32 sb  = (sb0 + 1023u) & ~1023u;
    char* smem_ptr = smem_raw + (sb - sb0);

    const int tid  = threadIdx.x;
    const int lane = tid & 31, wid = tid >> 5;
    const int wm = wid & 1, wn = wid >> 1;          // 2 x 4 warp grid
    const int m0 = blockIdx.x * 128, n0 = blockIdx.y * 128;
    const long long z = blockIdx.z;
    A += z * sAz; B += z * sBz;

    float acc[4][4][4];
    #pragma unroll
    for (int i = 0; i < 4; ++i)
        #pragma unroll
        for (int j = 0; j < 4; ++j)
            #pragma unroll
            for (int e = 0; e < 4; ++e) acc[i][j][e] = 0.f;

    // ---- cp.async loader: thread t -> row t/2, 4x16B chunks at c16=(t&1)*4 ----
    const int lr  = tid >> 1;
    const int lc0 = (tid & 1) * 4;                  // c16 base (0 or 4)
    const float* gA = A + (size_t)(m0 + lr) * lda + lc0 * 4;
    const float* gB = B + (size_t)(n0 + lr) * ldb + lc0 * 4;
    u32 swoff[4];
    #pragma unroll
    for (int j = 0; j < 4; ++j)
        swoff[j] = (u32)lr * 128u + (u32)(((lc0 + j) ^ (lr & 7)) << 4);

    auto load_stage = [&](int s, int k0) {          // k0 in fp32 elements
        const u32 b = sb + (u32)s * ST_BYTES;
        #pragma unroll
        for (int j = 0; j < 4; ++j) {
            cpa16(b +           swoff[j], gA + k0 + j * 4);
            cpa16(b + 16384u +  swoff[j], gB + k0 + j * 4);
        }
        CP_COMMIT();
    };

    const int nch = K >> 5;
    load_stage(0, 0);
    load_stage(1, 32);   // all our K >= 1024 -> nch >= 32

    // ---- ldmatrix lane maps ----
    // A frag (m16n8k8 tf32): a0..a3 = 8x4 fp32 tiles; lane group g=lane>>3:
    //   row = am*16 + (g&1)*8 + (lane&7),  c16 = ks*2 + (g>>1)
    // B frag: b0,b1 = 8x4 tiles of [n][k]; lanes 0-15: row n = bn*8 + (lane&7),
    //   c16 = ks*2 + ((lane>>3)&1)
    const int rr  = lane & 7;
    const int gA4 = lane >> 3;
    const int g2A = gA4 >> 1;
    const int gB1 = (lane >> 3) & 1;
    const u32 aRowBase = (u32)(wm * 64 + ((gA4 & 1) << 3) + rr) * 128u;
    const u32 bRowBase = (u32)(wn * 32 + rr) * 128u;
    u32 cAo[4], cBo[4];
    #pragma unroll
    for (int ks = 0; ks < 4; ++ks) {
        cAo[ks] = (u32)(((ks * 2 + g2A) ^ rr) << 4);
        cBo[ks] = (u32)(((ks * 2 + gB1) ^ rr) << 4);
    }

    int sc = 0;
    for (int c = 0; c < nch; ++c) {
        if (c + 1 < nch) { CP_WAIT(1); } else { CP_WAIT(0); }
        __syncthreads();

        if (c + 2 < nch) {
            int sl = sc + 2; if (sl >= NSTAGE) sl -= NSTAGE;
            load_stage(sl, (c + 2) * 32);
        }

        const u32 base = sb + (u32)sc * ST_BYTES;
        #pragma unroll
        for (int ks = 0; ks < 4; ++ks) {
            u32 bb[4][2];
            #pragma unroll
            for (int bn = 0; bn < 4; ++bn)
                LDSM2(bb[bn][0], bb[bn][1],
                      base + 16384u + bRowBase + (u32)bn * 1024u + cBo[ks]);
            #pragma unroll
            for (int am = 0; am < 4; ++am) {
                u32 aa[4];
                LDSM4(aa[0], aa[1], aa[2], aa[3],
                      base + aRowBase + (u32)am * 2048u + cAo[ks]);
                #pragma unroll
                for (int bn = 0; bn < 4; ++bn)
                    mma_tf32(acc[am][bn], aa, bb[bn]);
            }
        }
        if (++sc >= NSTAGE) sc -= NSTAGE;
    }

    // ======================= epilogue =======================
    const int q = lane >> 2, tq = lane & 3;

    if constexpr (MODE == 1) {
        __syncthreads();
        // transpose 128x128 tile through smem (u32 = tf32-rounded fp32 bits), stride 132
        u32* T = reinterpret_cast<u32*>(smem_ptr);
        #pragma unroll
        for (int am = 0; am < 4; ++am)
            #pragma unroll
            for (int bn = 0; bn < 4; ++bn)
                #pragma unroll
                for (int e = 0; e < 4; ++e) {
                    const int ml = wm * 64 + am * 16 + q + (e >> 1) * 8;
                    const int nl = wn * 32 + bn * 8 + 2 * tq + (e & 1);
                    T[nl * 132 + ml] = tf32r(acc[am][bn][e] + bias[n0 + nl]);
                }
        __syncthreads();
        const int d  = tid >> 1;
        const int mh = (tid & 1) * 64;
        const int b  = m0 >> 11;
        const size_t idx = ((size_t)b * CC + (n0 + d)) * TT + (m0 & 2047) + mh;
        u32* og = reinterpret_cast<u32*>(outF);
        #pragma unroll
        for (int i = 0; i < 64; i += 4) {
            uint4 w = make_uint4(T[d * 132 + mh + i],     T[d * 132 + mh + i + 1],
                                 T[d * 132 + mh + i + 2], T[d * 132 + mh + i + 3]);
            *reinterpret_cast<uint4*>(og + idx + i) = w;
        }
        return;
    } else {

    outF += z * sCz;
    #pragma unroll
    for (int am = 0; am < 4; ++am)
        #pragma unroll
        for (int e2 = 0; e2 < 2; ++e2) {
            const int gm = m0 + wm * 64 + am * 16 + q + e2 * 8;
            #pragma unroll
            for (int bn = 0; bn < 4; ++bn) {
                const int gn = n0 + wn * 32 + bn * 8 + 2 * tq;
                float v0 = acc[am][bn][e2 * 2 + 0];
                float v1 = acc[am][bn][e2 * 2 + 1];
                float2 val;
                if (MODE == 0) {
                    if (bias) { v0 += bias[gn]; v1 += bias[gn + 1]; }
                    val.x = tf32f(v0); val.y = tf32f(v1);
                } else if (MODE == 2) {
                    val.x = v0 * scale; val.y = v1 * scale;
                } else {
                    val.x = v0 + bias[gn]; val.y = v1 + bias[gn + 1];
                }
                *reinterpret_cast<float2*>(outF + (size_t)gm * ldc + gn) = val;
            }
        }
    }
}

// ======================= round fp32 -> tf32 =======================
__global__ void __launch_bounds__(256) round_kernel(
    const float* __restrict__ x, float* __restrict__ o, int n4)
{
    int i = blockIdx.x * 256 + threadIdx.x;
    if (i >= n4) return;
    float4 v = reinterpret_cast<const float4*>(x)[i];
    v.x = tf32f(v.x); v.y = tf32f(v.y); v.z = tf32f(v.z); v.w = tf32f(v.w);
    reinterpret_cast<float4*>(o)[i] = v;
}

__global__ void __launch_bounds__(256) round_w4_kernel(
    const float* __restrict__ w0, const float* __restrict__ w1,
    const float* __restrict__ w2, const float* __restrict__ w3,
    float* __restrict__ o)
{
    const int mat = blockIdx.y;
    const float* src = (mat == 0) ? w0 : (mat == 1) ? w1 : (mat == 2) ? w2 : w3;
    const size_t off4 = (size_t)mat * (CC * CC / 4);
    int i = blockIdx.x * 256 + threadIdx.x;
    float4 v = reinterpret_cast<const float4*>(src)[i];
    v.x = tf32f(v.x); v.y = tf32f(v.y); v.z = tf32f(v.z); v.w = tf32f(v.w);
    reinterpret_cast<float4*>(o)[off4 + i] = v;
}

// ======================= softmax (fp32 in, tf32-rounded fp32 out) =======================
__global__ void __launch_bounds__(256) softmax_kernel(
    const float* __restrict__ S, float* __restrict__ P)
{
    __shared__ float red[8];
    __shared__ float sM, sInv;
    const size_t row = blockIdx.x;
    const float4* src = reinterpret_cast<const float4*>(S + row * TT);
    const int t = threadIdx.x, w = t >> 5, ln = t & 31;

    float4 a = src[t], b2 = src[t + 256];
    float mx = fmaxf(fmaxf(fmaxf(a.x, a.y), fmaxf(a.z, a.w)),
                     fmaxf(fmaxf(b2.x, b2.y), fmaxf(b2.z, b2.w)));
    #pragma unroll
    for (int o = 16; o; o >>= 1) mx = fmaxf(mx, __shfl_xor_sync(0xffffffffu, mx, o));
    if (ln == 0) red[w] = mx;
    __syncthreads();
    if (t == 0) {
        float m = red[0];
        #pragma unroll
        for (int i = 1; i < 8; ++i) m = fmaxf(m, red[i]);
        sM = m;
    }
    __syncthreads();
    const float M = sM;

    float e[8];
    e[0] = __expf(a.x - M);  e[1] = __expf(a.y - M);
    e[2] = __expf(a.z - M);  e[3] = __expf(a.w - M);
    e[4] = __expf(b2.x - M); e[5] = __expf(b2.y - M);
    e[6] = __expf(b2.z - M); e[7] = __expf(b2.w - M);
    float sm = e[0]+e[1]+e[2]+e[3]+e[4]+e[5]+e[6]+e[7];
    #pragma unroll
    for (int o = 16; o; o >>= 1) sm += __shfl_xor_sync(0xffffffffu, sm, o);
    __syncthreads();
    if (ln == 0) red[w] = sm;
    __syncthreads();
    if (t == 0) {
        float ssum = 0.f;
        #pragma unroll
        for (int i = 0; i < 8; ++i) ssum += red[i];
        sInv = 1.0f / ssum;
    }
    __syncthreads();
    const float inv = sInv;

    #pragma unroll
    for (int half = 0; half < 2; ++half) {
        float4 o;
        o.x = tf32f(e[half*4 + 0] * inv);
        o.y = tf32f(e[half*4 + 1] * inv);
        o.z = tf32f(e[half*4 + 2] * inv);
        o.w = tf32f(e[half*4 + 3] * inv);
        size_t off = row * TT + (size_t)(t + half*256) * 4;
        *reinterpret_cast<float4*>(P + off) = o;
    }
}

// ======================= host launch =======================
static void* sym_addr(const void* s) {
    void* p = nullptr;
    cudaGetSymbolAddress(&p, s);
    return p;
}

extern "C" void kernel_launch(void* const* d_in, const int* in_sizes, int n_in,
                              void* d_out, int out_size) {
    (void)in_sizes; (void)n_in; (void)out_size;
    const float* x  = (const float*)d_in[0];
    const float* Wq = (const float*)d_in[1];
    const float* bq = (const float*)d_in[2];
    const float* Wk = (const float*)d_in[3];
    const float* bk = (const float*)d_in[4];
    const float* Wv = (const float*)d_in[5];
    const float* bv = (const float*)d_in[6];
    const float* Wo = (const float*)d_in[7];
    const float* bo = (const float*)d_in[8];
    float* out = (float*)d_out;

    float* xr = (float*)sym_addr(g_xr);
    float* wr = (float*)sym_addr(g_wr);
    float* qq = (float*)sym_addr(g_q);
    float* kk = (float*)sym_addr(g_k);
    float* vt = (float*)sym_addr(g_vt);
    float* sS = (float*)sym_addr(g_s);
    float* pp = (float*)sym_addr(g_p);
    float* cc = (float*)sym_addr(g_c);

    cudaFuncSetAttribute(gemm_tf32<0>, cudaFuncAttributeMaxDynamicSharedMemorySize, SMEM_BYTES);
    cudaFuncSetAttribute(gemm_tf32<1>, cudaFuncAttributeMaxDynamicSharedMemorySize, SMEM_BYTES);
    cudaFuncSetAttribute(gemm_tf32<2>, cudaFuncAttributeMaxDynamicSharedMemorySize, SMEM_BYTES);
    cudaFuncSetAttribute(gemm_tf32<3>, cudaFuncAttributeMaxDynamicSharedMemorySize, SMEM_BYTES);

    // round inputs to tf32
    round_kernel<<<(MROWS*CC/4 + 255)/256, 256>>>(x, xr, MROWS*CC/4);
    dim3 gW(CC*CC/4/256, 4);
    round_w4_kernel<<<gW, 256>>>(Wq, Wk, Wv, Wo, wr);

    dim3 gProj(MROWS/128, CC/128, 1);     // (64, 8, 1)
    // Q = x Wq^T + bq (tf32-rounded out)
    gemm_tf32<0><<<gProj, 256, SMEM_BYTES>>>(xr, wr + 0*(size_t)CC*CC,
        CC, CC, CC, 0, 0, 0, bq, 1.f, qq, CC);
    // K
    gemm_tf32<0><<<gProj, 256, SMEM_BYTES>>>(xr, wr + 1*(size_t)CC*CC,
        CC, CC, CC, 0, 0, 0, bk, 1.f, kk, CC);
    // V -> transposed store vt[b][d][s]
    gemm_tf32<1><<<gProj, 256, SMEM_BYTES>>>(xr, wr + 2*(size_t)CC*CC,
        CC, CC, CC, 0, 0, 0, bv, 1.f, vt, 0);

    // scores = Q K^T / 32 (per batch, full fp32)
    dim3 gScore(TT/128, TT/128, BN);      // (16, 16, 4)
    gemm_tf32<2><<<gScore, 256, SMEM_BYTES>>>(qq, kk,
        CC, CC, CC, (long long)TT*CC, (long long)TT*CC, (long long)TT*TT,
        nullptr, 0.03125f, sS, TT);

    // softmax (writes tf32-rounded P)
    softmax_kernel<<<MROWS, 256>>>(sS, pp);

    // ctx = P V  (A = P [t][s], B = vt [d][s], per batch; tf32-rounded out)
    dim3 gPV(TT/128, CC/128, BN);         // (16, 8, 4)
    gemm_tf32<0><<<gPV, 256, SMEM_BYTES>>>(pp, vt,
        TT, TT, TT, (long long)TT*TT, (long long)CC*TT, (long long)TT*CC,
        nullptr, 1.f, cc, CC);

    // out = ctx Wo^T + bo (fp32 -> d_out)
    gemm_tf32<3><<<gProj, 256, SMEM_BYTES>>>(cc, wr + 3*(size_t)CC*CC,
        CC, CC, CC, 0, 0, 0, bo, 1.f, out, CC);
}

// round 12
// speedup vs baseline: 1.9285x; 1.5311x over previous
#include <cuda_runtime.h>
#include <cuda_fp16.h>
#include <cstdint>
#include <cstddef>

typedef unsigned int u32;

#define BN 4
#define TT 2048
#define CC 1024
#define MROWS (BN*TT)   // 8192

// ======================= device scratch (no allocs allowed) =======================
__device__ __align__(256) __half g_xh[MROWS*CC];                 // 16MB
__device__ __align__(256) __half g_wh[4*CC*CC];                  // 8MB
__device__ __align__(256) __half g_q [MROWS*CC];                 // 16MB
__device__ __align__(256) __half g_k [MROWS*CC];                 // 16MB
__device__ __align__(256) __half g_vt[MROWS*CC];                 // V^T [b][d][s]
__device__ __align__(256) float  g_s [(size_t)BN*TT*TT];         // 64MB
__device__ __align__(256) __half g_p [(size_t)BN*TT*TT];         // 32MB
__device__ __align__(256) __half g_c [MROWS*CC];                 // 16MB

// ======================= PTX helpers (sm_100 baseline, NO 'a' features) =======================
__device__ __forceinline__ u32 smem_u32(const void* p) {
    u32 a;
    asm("{ .reg .u64 t; cvta.to.shared.u64 t, %1; cvt.u32.u64 %0, t; }" : "=r"(a) : "l"(p));
    return a;
}
__device__ __forceinline__ void cpa16(u32 dst, const void* src) {
    asm volatile("cp.async.cg.shared.global [%0], [%1], 16;" :: "r"(dst), "l"(src) : "memory");
}
#define CP_COMMIT() asm volatile("cp.async.commit_group;" ::: "memory")
#define CP_WAIT(n)  asm volatile("cp.async.wait_group %0;" :: "n"(n) : "memory")

#define LDSM4(d0,d1,d2,d3,a) \
    asm volatile("ldmatrix.sync.aligned.m8n8.x4.shared.b16 {%0,%1,%2,%3}, [%4];" \
                 : "=r"(d0),"=r"(d1),"=r"(d2),"=r"(d3) : "r"(a))
#define LDSM2(d0,d1,a) \
    asm volatile("ldmatrix.sync.aligned.m8n8.x2.shared.b16 {%0,%1}, [%2];" \
                 : "=r"(d0),"=r"(d1) : "r"(a))

__device__ __forceinline__ void mma_f16(float* c, const u32* a, const u32* b) {
    asm volatile(
        "mma.sync.aligned.m16n8k16.row.col.f32.f16.f16.f32 "
        "{%0,%1,%2,%3}, {%4,%5,%6,%7}, {%8,%9}, {%0,%1,%2,%3};"
        : "+f"(c[0]), "+f"(c[1]), "+f"(c[2]), "+f"(c[3])
        : "r"(a[0]), "r"(a[1]), "r"(a[2]), "r"(a[3]), "r"(b[0]), "r"(b[1]));
}

__device__ __forceinline__ u32 pack_h2(__half a, __half b) {
    __half2 t = __halves2half2(a, b);
    return *reinterpret_cast<u32*>(&t);
}
__device__ __forceinline__ unsigned short h_bits(__half h) {
    return *reinterpret_cast<unsigned short*>(&h);
}

// 64B-row swizzle: row*64 + ((c16 ^ ((row>>1)&3)) << 4); bijective over the 8
// 16B slots per 128B phase; additive in row steps of 8/16.
__device__ __forceinline__ u32 swz64(int row, int c16) {
    return (u32)row * 64u + (u32)((c16 ^ ((row >> 1) & 3)) << 4);
}

// ======================= GEMM kernel =======================
// Tile 128x128, K-chunk 32 (half). Stage: A(8K) + B(8K) = 16KB; 3 stages; 2 CTAs/SM.
#define ST_BYTES   16384u
#define NSTAGE     3
#define SMEM_BYTES (1024 + NSTAGE*16384 + 68*1024)   // stages + transpose buffer slack

// MODE 0: half out (+optional bias, +batch stride on C)         [Q,K,P->ctx]
// MODE 1: V-projection: bias then transposed half store into vt[b][d][s]
// MODE 2: fp32 * scale out (+batch stride on C)                 [scores]
// MODE 3: fp32 + bias out (final output)
template<int MODE>
__global__ void __launch_bounds__(256, 2) gemm_f16(
    const __half* __restrict__ A, const __half* __restrict__ B,
    int lda, int ldb, int K,
    long long sAz, long long sBz, long long sCz,
    const float* __restrict__ bias, float scale,
    __half* __restrict__ outH, float* __restrict__ outF, int ldc)
{
    extern __shared__ __align__(1024) char smem_raw[];
    const u32 sb0 = smem_u32(smem_raw);
    const u32 sb  = (sb0 + 1023u) & ~1023u;
    char* smem_ptr = smem_raw + (sb - sb0);

    const int tid  = threadIdx.x;
    const int lane = tid & 31, wid = tid >> 5;
    const int wm = wid & 1, wn = wid >> 1;          // 2 x 4 warp grid
    const int m0 = blockIdx.x * 128, n0 = blockIdx.y * 128;
    const long long z = blockIdx.z;
    A += z * sAz; B += z * sBz;

    float acc[4][4][4];
    #pragma unroll
    for (int i = 0; i < 4; ++i)
        #pragma unroll
        for (int j = 0; j < 4; ++j)
            #pragma unroll
            for (int e = 0; e < 4; ++e) acc[i][j][e] = 0.f;

    // ---- cp.async loader: thread t -> row t/2, 2x16B chunks at c16=(t&1)*2 ----
    const int lr  = tid >> 1;
    const int lc0 = (tid & 1) * 2;
    const __half* gA = A + (size_t)(m0 + lr) * lda + lc0 * 8;
    const __half* gB = B + (size_t)(n0 + lr) * ldb + lc0 * 8;

    auto load_stage = [&](int s, int k0) {
        const u32 b = sb + (u32)s * ST_BYTES;
        #pragma unroll
        for (int j = 0; j < 2; ++j) {
            const u32 dst = b + swz64(lr, lc0 + j);
            cpa16(dst,          gA + k0 + j * 8);
            cpa16(dst + 8192u,  gB + k0 + j * 8);
        }
        CP_COMMIT();
    };

    const int nch = K >> 5;
    load_stage(0, 0);
    load_stage(1, 32);

    const int rA = lane & 15, cA = lane >> 4;          // ldmatrix x4 lane map (A)
    const int rB = lane & 7,  cB = (lane >> 3) & 1;    // ldmatrix x2 lane map (B)

    // loop-invariant swizzled offsets
    const u32 offA0 = swz64(wm * 64 + rA, cA);
    const u32 offA1 = swz64(wm * 64 + rA, 2 + cA);
    const u32 offB0 = swz64(wn * 32 + rB, cB);
    const u32 offB1 = swz64(wn * 32 + rB, 2 + cB);

    int sc = 0;
    for (int c = 0; c < nch; ++c) {
        if (c + 1 < nch) { CP_WAIT(1); } else { CP_WAIT(0); }
        __syncthreads();

        if (c + 2 < nch) {
            int sl = sc + 2; if (sl >= NSTAGE) sl -= NSTAGE;
            load_stage(sl, (c + 2) * 32);
        }

        const u32 base = sb + (u32)sc * ST_BYTES;
        #pragma unroll
        for (int ks = 0; ks < 2; ++ks) {
            const u32 aoff = base + (ks ? offA1 : offA0);
            const u32 boff = base + 8192u + (ks ? offB1 : offB0);

            u32 bb[4][2];
            #pragma unroll
            for (int bn = 0; bn < 4; ++bn)
                LDSM2(bb[bn][0], bb[bn][1], boff + (u32)bn * 512u);

            #pragma unroll
            for (int am = 0; am < 4; ++am) {
                u32 aa[4];
                LDSM4(aa[0], aa[1], aa[2], aa[3], aoff + (u32)am * 1024u);
                #pragma unroll
                for (int bn = 0; bn < 4; ++bn)
                    mma_f16(acc[am][bn], aa, bb[bn]);
            }
        }
        if (++sc >= NSTAGE) sc -= NSTAGE;
    }

    // ======================= epilogue =======================
    const int q = lane >> 2, tq = lane & 3;

    if constexpr (MODE == 1) {
        __syncthreads();
        // transpose 128x128 tile through smem (u32 slot = one half), stride 132
        u32* T = reinterpret_cast<u32*>(smem_ptr);
        #pragma unroll
        for (int am = 0; am < 4; ++am)
            #pragma unroll
            for (int bn = 0; bn < 4; ++bn)
                #pragma unroll
                for (int e = 0; e < 4; ++e) {
                    const int ml = wm * 64 + am * 16 + q + (e >> 1) * 8;
                    const int nl = wn * 32 + bn * 8 + 2 * tq + (e & 1);
                    T[nl * 132 + ml] = (u32)h_bits(__float2half_rn(acc[am][bn][e] + bias[n0 + nl]));
                }
        __syncthreads();
        const int d  = tid >> 1;
        const int mh = (tid & 1) * 64;
        const int b  = m0 >> 11;
        const size_t idx = ((size_t)b * CC + (n0 + d)) * TT + (m0 & 2047) + mh;
        #pragma unroll
        for (int i = 0; i < 64; i += 8) {
            u32 w[4];
            #pragma unroll
            for (int p = 0; p < 4; ++p) {
                const u32 t0 = T[d * 132 + mh + i + 2 * p];
                const u32 t1 = T[d * 132 + mh + i + 2 * p + 1];
                w[p] = (t0 & 0xffffu) | (t1 << 16);
            }
            *reinterpret_cast<uint4*>(outH + idx + i) = make_uint4(w[0], w[1], w[2], w[3]);
        }
        return;
    } else {

    if (MODE == 0) outH += z * sCz;
    else           outF += z * sCz;

    #pragma unroll
    for (int am = 0; am < 4; ++am)
        #pragma unroll
        for (int e2 = 0; e2 < 2; ++e2) {
            const int gm = m0 + wm * 64 + am * 16 + q + e2 * 8;
            #pragma unroll
            for (int bn = 0; bn < 4; ++bn) {
                const int gn = n0 + wn * 32 + bn * 8 + 2 * tq;
                float v0 = acc[am][bn][e2 * 2 + 0];
                float v1 = acc[am][bn][e2 * 2 + 1];
                if (MODE == 0) {
                    if (bias) { v0 += bias[gn]; v1 += bias[gn + 1]; }
                    *reinterpret_cast<u32*>(outH + (size_t)gm * ldc + gn) =
                        pack_h2(__float2half_rn(v0), __float2half_rn(v1));
                } else if (MODE == 2) {
                    float2 val; val.x = v0 * scale; val.y = v1 * scale;
                    *reinterpret_cast<float2*>(outF + (size_t)gm * ldc + gn) = val;
                } else {
                    float2 val; val.x = v0 + bias[gn]; val.y = v1 + bias[gn + 1];
                    *reinterpret_cast<float2*>(outF + (size_t)gm * ldc + gn) = val;
                }
            }
        }
    }
}

// ======================= convert fp32 -> half =======================
__global__ void __launch_bounds__(256) cvt_kernel(
    const float* __restrict__ x, __half* __restrict__ o, int n4)
{
    int i = blockIdx.x * 256 + threadIdx.x;
    if (i >= n4) return;
    float4 v = reinterpret_cast<const float4*>(x)[i];
    uint2 w;
    w.x = pack_h2(__float2half_rn(v.x), __float2half_rn(v.y));
    w.y = pack_h2(__float2half_rn(v.z), __float2half_rn(v.w));
    *reinterpret_cast<uint2*>(o + 4*(size_t)i) = w;
}

__global__ void __launch_bounds__(256) cvt_w4_kernel(
    const float* __restrict__ w0, const float* __restrict__ w1,
    const float* __restrict__ w2, const float* __restrict__ w3,
    __half* __restrict__ o)
{
    const int mat = blockIdx.y;
    const float* src = (mat == 0) ? w0 : (mat == 1) ? w1 : (mat == 2) ? w2 : w3;
    const size_t off = (size_t)mat * CC * CC;
    int i = blockIdx.x * 256 + threadIdx.x;
    float4 v = reinterpret_cast<const float4*>(src)[i];
    uint2 w;
    w.x = pack_h2(__float2half_rn(v.x), __float2half_rn(v.y));
    w.y = pack_h2(__float2half_rn(v.z), __float2half_rn(v.w));
    *reinterpret_cast<uint2*>(o + off + 4*(size_t)i) = w;
}

// ======================= softmax (fp32 in, half out) =======================
__global__ void __launch_bounds__(256) softmax_kernel(
    const float* __restrict__ S, __half* __restrict__ P)
{
    __shared__ float red[8];
    __shared__ float sM, sInv;
    const size_t row = blockIdx.x;
    const float4* src = reinterpret_cast<const float4*>(S + row * TT);
    const int t = threadIdx.x, w = t >> 5, ln = t & 31;

    float4 a = src[t], b2 = src[t + 256];
    float mx = fmaxf(fmaxf(fmaxf(a.x, a.y), fmaxf(a.z, a.w)),
                     fmaxf(fmaxf(b2.x, b2.y), fmaxf(b2.z, b2.w)));
    #pragma unroll
    for (int o = 16; o; o >>= 1) mx = fmaxf(mx, __shfl_xor_sync(0xffffffffu, mx, o));
    if (ln == 0) red[w] = mx;
    __syncthreads();
    if (t == 0) {
        float m = red[0];
        #pragma unroll
        for (int i = 1; i < 8; ++i) m = fmaxf(m, red[i]);
        sM = m;
    }
    __syncthreads();
    const float M = sM;

    float e[8];
    e[0] = __expf(a.x - M);  e[1] = __expf(a.y - M);
    e[2] = __expf(a.z - M);  e[3] = __expf(a.w - M);
    e[4] = __expf(b2.x - M); e[5] = __expf(b2.y - M);
    e[6] = __expf(b2.z - M); e[7] = __expf(b2.w - M);
    float sm = e[0]+e[1]+e[2]+e[3]+e[4]+e[5]+e[6]+e[7];
    #pragma unroll
    for (int o = 16; o; o >>= 1) sm += __shfl_xor_sync(0xffffffffu, sm, o);
    __syncthreads();
    if (ln == 0) red[w] = sm;
    __syncthreads();
    if (t == 0) {
        float ssum = 0.f;
        #pragma unroll
        for (int i = 0; i < 8; ++i) ssum += red[i];
        sInv = 1.0f / ssum;
    }
    __syncthreads();
    const float inv = sInv;

    #pragma unroll
    for (int half = 0; half < 2; ++half) {
        uint2 w2o;
        w2o.x = pack_h2(__float2half_rn(e[half*4 + 0] * inv), __float2half_rn(e[half*4 + 1] * inv));
        w2o.y = pack_h2(__float2half_rn(e[half*4 + 2] * inv), __float2half_rn(e[half*4 + 3] * inv));
        size_t off = row * TT + (size_t)(t + half*256) * 4;
        *reinterpret_cast<uint2*>(P + off) = w2o;
    }
}

// ======================= host launch =======================
static void* sym_addr(const void* s) {
    void* p = nullptr;
    cudaGetSymbolAddress(&p, s);
    return p;
}

extern "C" void kernel_launch(void* const* d_in, const int* in_sizes, int n_in,
                              void* d_out, int out_size) {
    (void)in_sizes; (void)n_in; (void)out_size;
    const float* x  = (const float*)d_in[0];
    const float* Wq = (const float*)d_in[1];
    const float* bq = (const float*)d_in[2];
    const float* Wk = (const float*)d_in[3];
    const float* bk = (const float*)d_in[4];
    const float* Wv = (const float*)d_in[5];
    const float* bv = (const float*)d_in[6];
    const float* Wo = (const float*)d_in[7];
    const float* bo = (const float*)d_in[8];
    float* out = (float*)d_out;

    __half* xh = (__half*)sym_addr(g_xh);
    __half* wh = (__half*)sym_addr(g_wh);
    __half* qq = (__half*)sym_addr(g_q);
    __half* kk = (__half*)sym_addr(g_k);
    __half* vt = (__half*)sym_addr(g_vt);
    float*  sS = (float*)sym_addr(g_s);
    __half* pp = (__half*)sym_addr(g_p);
    __half* cc = (__half*)sym_addr(g_c);

    cudaFuncSetAttribute(gemm_f16<0>, cudaFuncAttributeMaxDynamicSharedMemorySize, SMEM_BYTES);
    cudaFuncSetAttribute(gemm_f16<1>, cudaFuncAttributeMaxDynamicSharedMemorySize, SMEM_BYTES);
    cudaFuncSetAttribute(gemm_f16<2>, cudaFuncAttributeMaxDynamicSharedMemorySize, SMEM_BYTES);
    cudaFuncSetAttribute(gemm_f16<3>, cudaFuncAttributeMaxDynamicSharedMemorySize, SMEM_BYTES);

    // convert inputs to half
    cvt_kernel<<<(MROWS*CC/4 + 255)/256, 256>>>(x, xh, MROWS*CC/4);
    dim3 gW(CC*CC/4/256, 4);
    cvt_w4_kernel<<<gW, 256>>>(Wq, Wk, Wv, Wo, wh);

    dim3 gProj(MROWS/128, CC/128, 1);     // (64, 8, 1)
    // Q = x Wq^T + bq (half out)
    gemm_f16<0><<<gProj, 256, SMEM_BYTES>>>(xh, wh + 0*(size_t)CC*CC,
        CC, CC, CC, 0, 0, 0, bq, 1.f, qq, nullptr, CC);
    // K
    gemm_f16<0><<<gProj, 256, SMEM_BYTES>>>(xh, wh + 1*(size_t)CC*CC,
        CC, CC, CC, 0, 0, 0, bk, 1.f, kk, nullptr, CC);
    // V -> transposed half store vt[b][d][s]
    gemm_f16<1><<<gProj, 256, SMEM_BYTES>>>(xh, wh + 2*(size_t)CC*CC,
        CC, CC, CC, 0, 0, 0, bv, 1.f, vt, nullptr, 0);

    // scores = Q K^T / 32 (per batch, fp32 out)
    dim3 gScore(TT/128, TT/128, BN);      // (16, 16, 4)
    gemm_f16<2><<<gScore, 256, SMEM_BYTES>>>(qq, kk,
        CC, CC, CC, (long long)TT*CC, (long long)TT*CC, (long long)TT*TT,
        nullptr, 0.03125f, nullptr, sS, TT);

    // softmax (writes half P)
    softmax_kernel<<<MROWS, 256>>>(sS, pp);

    // ctx = P V (A = P [t][s], B = vt [d][s], per batch; half out)
    dim3 gPV(TT/128, CC/128, BN);         // (16, 8, 4)
    gemm_f16<0><<<gPV, 256, SMEM_BYTES>>>(pp, vt,
        TT, TT, TT, (long long)TT*TT, (long long)CC*TT, (long long)TT*CC,
        nullptr, 1.f, cc, nullptr, CC);

    // out = ctx Wo^T + bo (fp32 -> d_out)
    gemm_f16<3><<<gProj, 256, SMEM_BYTES>>>(cc, wh + 3*(size_t)CC*CC,
        CC, CC, CC, 0, 0, 0, bo, 1.f, nullptr, out, CC);
}

// round 13
// speedup vs baseline: 2.4071x; 1.2482x over previous
#include <cuda_runtime.h>
#include <cuda_fp16.h>
#include <cstdint>
#include <cstddef>

typedef unsigned int u32;
typedef unsigned short u16;

#define BN 4
#define TT 2048
#define CC 1024
#define MROWS (BN*TT)   // 8192

// ======================= device scratch (no allocs allowed) =======================
__device__ __align__(256) __half g_xh[MROWS*CC];
__device__ __align__(256) __half g_wh[4*CC*CC];
__device__ __align__(256) __half g_q [MROWS*CC];
__device__ __align__(256) __half g_k [MROWS*CC];
__device__ __align__(256) __half g_vt[MROWS*CC];                 // V^T [b][d][s]
__device__ __align__(256) float  g_s [(size_t)BN*TT*TT];
__device__ __align__(256) __half g_p [(size_t)BN*TT*TT];
__device__ __align__(256) __half g_c [MROWS*CC];

// ======================= PTX helpers (sm_100 baseline, NO 'a' features) =======================
__device__ __forceinline__ u32 smem_u32(const void* p) {
    u32 a;
    asm("{ .reg .u64 t; cvta.to.shared.u64 t, %1; cvt.u32.u64 %0, t; }" : "=r"(a) : "l"(p));
    return a;
}
__device__ __forceinline__ void cpa16(u32 dst, const void* src) {
    asm volatile("cp.async.cg.shared.global [%0], [%1], 16;" :: "r"(dst), "l"(src) : "memory");
}
#define CP_COMMIT() asm volatile("cp.async.commit_group;" ::: "memory")
#define CP_WAIT(n)  asm volatile("cp.async.wait_group %0;" :: "n"(n) : "memory")

#define LDSM4(d0,d1,d2,d3,a) \
    asm volatile("ldmatrix.sync.aligned.m8n8.x4.shared.b16 {%0,%1,%2,%3}, [%4];" \
                 : "=r"(d0),"=r"(d1),"=r"(d2),"=r"(d3) : "r"(a))
#define LDSM2(d0,d1,a) \
    asm volatile("ldmatrix.sync.aligned.m8n8.x2.shared.b16 {%0,%1}, [%2];" \
                 : "=r"(d0),"=r"(d1) : "r"(a))

__device__ __forceinline__ void mma_f16(float* c, const u32* a, const u32* b) {
    asm volatile(
        "mma.sync.aligned.m16n8k16.row.col.f32.f16.f16.f32 "
        "{%0,%1,%2,%3}, {%4,%5,%6,%7}, {%8,%9}, {%0,%1,%2,%3};"
        : "+f"(c[0]), "+f"(c[1]), "+f"(c[2]), "+f"(c[3])
        : "r"(a[0]), "r"(a[1]), "r"(a[2]), "r"(a[3]), "r"(b[0]), "r"(b[1]));
}

__device__ __forceinline__ u32 pack_h2(__half a, __half b) {
    __half2 t = __halves2half2(a, b);
    return *reinterpret_cast<u32*>(&t);
}
__device__ __forceinline__ u16 h_bits(__half h) {
    return *reinterpret_cast<u16*>(&h);
}

// 64B-row swizzle: row*64 + ((c16 ^ ((row>>1)&3)) << 4)
__device__ __forceinline__ u32 swz64(int row, int c16) {
    return (u32)row * 64u + (u32)((c16 ^ ((row >> 1) & 3)) << 4);
}

// ======================= GEMM kernel =======================
// Tile 128x128, K-chunk 32 (half). Stage: A(8K) + B(8K) = 16KB; 3 stages = 48KB.
// Transpose buffer (MODE 1) reuses the stage region as u16 (33.8KB <= 48KB).
// 49KB/CTA -> 2 CTAs/SM.
#define ST_BYTES   16384u
#define NSTAGE     3
#define SMEM_BYTES (1024 + NSTAGE*16384)   // 50176

// MODE 0: half out (+optional bias, +batch stride on C)         [Q,K,P->ctx]
// MODE 1: V-projection: bias then transposed half store into vt[b][d][s]
// MODE 2: fp32 * scale out (+batch stride on C)                 [scores]
// MODE 3: fp32 + bias out (final output)
template<int MODE>
__global__ void __launch_bounds__(256, 2) gemm_f16(
    const __half* __restrict__ A, const __half* __restrict__ B,
    int lda, int ldb, int K,
    long long sAz, long long sBz, long long sCz,
    const float* __restrict__ bias, float scale,
    __half* __restrict__ outH, float* __restrict__ outF, int ldc)
{
    extern __shared__ __align__(1024) char smem_raw[];
    const u32 sb0 = smem_u32(smem_raw);
    const u32 sb  = (sb0 + 1023u) & ~1023u;
    char* smem_ptr = smem_raw + (sb - sb0);

    const int tid  = threadIdx.x;
    const int lane = tid & 31, wid = tid >> 5;
    const int wm = wid & 1, wn = wid >> 1;          // 2 x 4 warp grid
    const int m0 = blockIdx.x * 128, n0 = blockIdx.y * 128;
    const long long z = blockIdx.z;
    A += z * sAz; B += z * sBz;

    float acc[4][4][4];
    #pragma unroll
    for (int i = 0; i < 4; ++i)
        #pragma unroll
        for (int j = 0; j < 4; ++j)
            #pragma unroll
            for (int e = 0; e < 4; ++e) acc[i][j][e] = 0.f;

    // ---- cp.async loader: thread t -> row t/2, 2x16B chunks at c16=(t&1)*2 ----
    const int lr  = tid >> 1;
    const int lc0 = (tid & 1) * 2;
    const __half* gA = A + (size_t)(m0 + lr) * lda + lc0 * 8;
    const __half* gB = B + (size_t)(n0 + lr) * ldb + lc0 * 8;

    auto load_stage = [&](int s, int k0) {
        const u32 b = sb + (u32)s * ST_BYTES;
        #pragma unroll
        for (int j = 0; j < 2; ++j) {
            const u32 dst = b + swz64(lr, lc0 + j);
            cpa16(dst,          gA + k0 + j * 8);
            cpa16(dst + 8192u,  gB + k0 + j * 8);
        }
        CP_COMMIT();
    };

    const int nch = K >> 5;
    load_stage(0, 0);
    load_stage(1, 32);

    const int rA = lane & 15, cA = lane >> 4;          // ldmatrix x4 lane map (A)
    const int rB = lane & 7,  cB = (lane >> 3) & 1;    // ldmatrix x2 lane map (B)

    const u32 offA0 = swz64(wm * 64 + rA, cA);
    const u32 offA1 = swz64(wm * 64 + rA, 2 + cA);
    const u32 offB0 = swz64(wn * 32 + rB, cB);
    const u32 offB1 = swz64(wn * 32 + rB, 2 + cB);

    int sc = 0;
    for (int c = 0; c < nch; ++c) {
        if (c + 1 < nch) { CP_WAIT(1); } else { CP_WAIT(0); }
        __syncthreads();

        if (c + 2 < nch) {
            int sl = sc + 2; if (sl >= NSTAGE) sl -= NSTAGE;
            load_stage(sl, (c + 2) * 32);
        }

        const u32 base = sb + (u32)sc * ST_BYTES;
        #pragma unroll
        for (int ks = 0; ks < 2; ++ks) {
            const u32 aoff = base + (ks ? offA1 : offA0);
            const u32 boff = base + 8192u + (ks ? offB1 : offB0);

            u32 bb[4][2];
            #pragma unroll
            for (int bn = 0; bn < 4; ++bn)
                LDSM2(bb[bn][0], bb[bn][1], boff + (u32)bn * 512u);

            #pragma unroll
            for (int am = 0; am < 4; ++am) {
                u32 aa[4];
                LDSM4(aa[0], aa[1], aa[2], aa[3], aoff + (u32)am * 1024u);
                #pragma unroll
                for (int bn = 0; bn < 4; ++bn)
                    mma_f16(acc[am][bn], aa, bb[bn]);
            }
        }
        if (++sc >= NSTAGE) sc -= NSTAGE;
    }

    // ======================= epilogue =======================
    const int q = lane >> 2, tq = lane & 3;

    if constexpr (MODE == 1) {
        __syncthreads();   // all warps done with stage smem before T-buffer overwrite
        // transpose 128x128 tile through smem (u16 = half bits), stride 132
        u16* T = reinterpret_cast<u16*>(smem_ptr);
        #pragma unroll
        for (int am = 0; am < 4; ++am)
            #pragma unroll
            for (int bn = 0; bn < 4; ++bn)
                #pragma unroll
                for (int e = 0; e < 4; ++e) {
                    const int ml = wm * 64 + am * 16 + q + (e >> 1) * 8;
                    const int nl = wn * 32 + bn * 8 + 2 * tq + (e & 1);
                    T[nl * 132 + ml] = h_bits(__float2half_rn(acc[am][bn][e] + bias[n0 + nl]));
                }
        __syncthreads();
        const int d  = tid >> 1;
        const int mh = (tid & 1) * 64;
        const int b  = m0 >> 11;
        const size_t idx = ((size_t)b * CC + (n0 + d)) * TT + (m0 & 2047) + mh;
        #pragma unroll
        for (int i = 0; i < 64; i += 8) {
            u32 w[4];
            #pragma unroll
            for (int p = 0; p < 4; ++p) {
                const u32 t0 = (u32)T[d * 132 + mh + i + 2 * p];
                const u32 t1 = (u32)T[d * 132 + mh + i + 2 * p + 1];
                w[p] = t0 | (t1 << 16);
            }
            *reinterpret_cast<uint4*>(outH + idx + i) = make_uint4(w[0], w[1], w[2], w[3]);
        }
        return;
    } else {

    if (MODE == 0) outH += z * sCz;
    else           outF += z * sCz;

    #pragma unroll
    for (int am = 0; am < 4; ++am)
        #pragma unroll
        for (int e2 = 0; e2 < 2; ++e2) {
            const int gm = m0 + wm * 64 + am * 16 + q + e2 * 8;
            #pragma unroll
            for (int bn = 0; bn < 4; ++bn) {
                const int gn = n0 + wn * 32 + bn * 8 + 2 * tq;
                float v0 = acc[am][bn][e2 * 2 + 0];
                float v1 = acc[am][bn][e2 * 2 + 1];
                if (MODE == 0) {
                    if (bias) { v0 += bias[gn]; v1 += bias[gn + 1]; }
                    *reinterpret_cast<u32*>(outH + (size_t)gm * ldc + gn) =
                        pack_h2(__float2half_rn(v0), __float2half_rn(v1));
                } else if (MODE == 2) {
                    float2 val; val.x = v0 * scale; val.y = v1 * scale;
                    *reinterpret_cast<float2*>(outF + (size_t)gm * ldc + gn) = val;
                } else {
                    float2 val; val.x = v0 + bias[gn]; val.y = v1 + bias[gn + 1];
                    *reinterpret_cast<float2*>(outF + (size_t)gm * ldc + gn) = val;
                }
            }
        }
    }
}

// ======================= convert fp32 -> half =======================
__global__ void __launch_bounds__(256) cvt_kernel(
    const float* __restrict__ x, __half* __restrict__ o, int n4)
{
    int i = blockIdx.x * 256 + threadIdx.x;
    if (i >= n4) return;
    float4 v = reinterpret_cast<const float4*>(x)[i];
    uint2 w;
    w.x = pack_h2(__float2half_rn(v.x), __float2half_rn(v.y));
    w.y = pack_h2(__float2half_rn(v.z), __float2half_rn(v.w));
    *reinterpret_cast<uint2*>(o + 4*(size_t)i) = w;
}

__global__ void __launch_bounds__(256) cvt_w4_kernel(
    const float* __restrict__ w0, const float* __restrict__ w1,
    const float* __restrict__ w2, const float* __restrict__ w3,
    __half* __restrict__ o)
{
    const int mat = blockIdx.y;
    const float* src = (mat == 0) ? w0 : (mat == 1) ? w1 : (mat == 2) ? w2 : w3;
    const size_t off = (size_t)mat * CC * CC;
    int i = blockIdx.x * 256 + threadIdx.x;
    float4 v = reinterpret_cast<const float4*>(src)[i];
    uint2 w;
    w.x = pack_h2(__float2half_rn(v.x), __float2half_rn(v.y));
    w.y = pack_h2(__float2half_rn(v.z), __float2half_rn(v.w));
    *reinterpret_cast<uint2*>(o + off + 4*(size_t)i) = w;
}

// ======================= softmax (fp32 in, half out) =======================
__global__ void __launch_bounds__(256) softmax_kernel(
    const float* __restrict__ S, __half* __restrict__ P)
{
    __shared__ float red[8];
    __shared__ float sM, sInv;
    const size_t row = blockIdx.x;
    const float4* src = reinterpret_cast<const float4*>(S + row * TT);
    const int t = threadIdx.x, w = t >> 5, ln = t & 31;

    float4 a = src[t], b2 = src[t + 256];
    float mx = fmaxf(fmaxf(fmaxf(a.x, a.y), fmaxf(a.z, a.w)),
                     fmaxf(fmaxf(b2.x, b2.y), fmaxf(b2.z, b2.w)));
    #pragma unroll
    for (int o = 16; o; o >>= 1) mx = fmaxf(mx, __shfl_xor_sync(0xffffffffu, mx, o));
    if (ln == 0) red[w] = mx;
    __syncthreads();
    if (t == 0) {
        float m = red[0];
        #pragma unroll
        for (int i = 1; i < 8; ++i) m = fmaxf(m, red[i]);
        sM = m;
    }
    __syncthreads();
    const float M = sM;

    float e[8];
    e[0] = __expf(a.x - M);  e[1] = __expf(a.y - M);
    e[2] = __expf(a.z - M);  e[3] = __expf(a.w - M);
    e[4] = __expf(b2.x - M); e[5] = __expf(b2.y - M);
    e[6] = __expf(b2.z - M); e[7] = __expf(b2.w - M);
    float sm = e[0]+e[1]+e[2]+e[3]+e[4]+e[5]+e[6]+e[7];
    #pragma unroll
    for (int o = 16; o; o >>= 1) sm += __shfl_xor_sync(0xffffffffu, sm, o);
    __syncthreads();
    if (ln == 0) red[w] = sm;
    __syncthreads();
    if (t == 0) {
        float ssum = 0.f;
        #pragma unroll
        for (int i = 0; i < 8; ++i) ssum += red[i];
        sInv = 1.0f / ssum;
    }
    __syncthreads();
    const float inv = sInv;

    #pragma unroll
    for (int half = 0; half < 2; ++half) {
        uint2 w2o;
        w2o.x = pack_h2(__float2half_rn(e[half*4 + 0] * inv), __float2half_rn(e[half*4 + 1] * inv));
        w2o.y = pack_h2(__float2half_rn(e[half*4 + 2] * inv), __float2half_rn(e[half*4 + 3] * inv));
        size_t off = row * TT + (size_t)(t + half*256) * 4;
        *reinterpret_cast<uint2*>(P + off) = w2o;
    }
}

// ======================= host launch =======================
static void* sym_addr(const void* s) {
    void* p = nullptr;
    cudaGetSymbolAddress(&p, s);
    return p;
}

extern "C" void kernel_launch(void* const* d_in, const int* in_sizes, int n_in,
                              void* d_out, int out_size) {
    (void)in_sizes; (void)n_in; (void)out_size;
    const float* x  = (const float*)d_in[0];
    const float* Wq = (const float*)d_in[1];
    const float* bq = (const float*)d_in[2];
    const float* Wk = (const float*)d_in[3];
    const float* bk = (const float*)d_in[4];
    const float* Wv = (const float*)d_in[5];
    const float* bv = (const float*)d_in[6];
    const float* Wo = (const float*)d_in[7];
    const float* bo = (const float*)d_in[8];
    float* out = (float*)d_out;

    __half* xh = (__half*)sym_addr(g_xh);
    __half* wh = (__half*)sym_addr(g_wh);
    __half* qq = (__half*)sym_addr(g_q);
    __half* kk = (__half*)sym_addr(g_k);
    __half* vt = (__half*)sym_addr(g_vt);
    float*  sS = (float*)sym_addr(g_s);
    __half* pp = (__half*)sym_addr(g_p);
    __half* cc = (__half*)sym_addr(g_c);

    cudaFuncSetAttribute(gemm_f16<0>, cudaFuncAttributeMaxDynamicSharedMemorySize, SMEM_BYTES);
    cudaFuncSetAttribute(gemm_f16<1>, cudaFuncAttributeMaxDynamicSharedMemorySize, SMEM_BYTES);
    cudaFuncSetAttribute(gemm_f16<2>, cudaFuncAttributeMaxDynamicSharedMemorySize, SMEM_BYTES);
    cudaFuncSetAttribute(gemm_f16<3>, cudaFuncAttributeMaxDynamicSharedMemorySize, SMEM_BYTES);

    // convert inputs to half
    cvt_kernel<<<(MROWS*CC/4 + 255)/256, 256>>>(x, xh, MROWS*CC/4);
    dim3 gW(CC*CC/4/256, 4);
    cvt_w4_kernel<<<gW, 256>>>(Wq, Wk, Wv, Wo, wh);

    dim3 gProj(MROWS/128, CC/128, 1);     // (64, 8, 1)
    // Q = x Wq^T + bq (half out)
    gemm_f16<0><<<gProj, 256, SMEM_BYTES>>>(xh, wh + 0*(size_t)CC*CC,
        CC, CC, CC, 0, 0, 0, bq, 1.f, qq, nullptr, CC);
    // K
    gemm_f16<0><<<gProj, 256, SMEM_BYTES>>>(xh, wh + 1*(size_t)CC*CC,
        CC, CC, CC, 0, 0, 0, bk, 1.f, kk, nullptr, CC);
    // V -> transposed half store vt[b][d][s]
    gemm_f16<1><<<gProj, 256, SMEM_BYTES>>>(xh, wh + 2*(size_t)CC*CC,
        CC, CC, CC, 0, 0, 0, bv, 1.f, vt, nullptr, 0);

    // scores = Q K^T / 32 (per batch, fp32 out)
    dim3 gScore(TT/128, TT/128, BN);      // (16, 16, 4)
    gemm_f16<2><<<gScore, 256, SMEM_BYTES>>>(qq, kk,
        CC, CC, CC, (long long)TT*CC, (long long)TT*CC, (long long)TT*TT,
        nullptr, 0.03125f, nullptr, sS, TT);

    // softmax (writes half P)
    softmax_kernel<<<MROWS, 256>>>(sS, pp);

    // ctx = P V (A = P [t][s], B = vt [d][s], per batch; half out)
    dim3 gPV(TT/128, CC/128, BN);         // (16, 8, 4)
    gemm_f16<0><<<gPV, 256, SMEM_BYTES>>>(pp, vt,
        TT, TT, TT, (long long)TT*TT, (long long)CC*TT, (long long)TT*CC,
        nullptr, 1.f, cc, nullptr, CC);

    // out = ctx Wo^T + bo (fp32 -> d_out)
    gemm_f16<3><<<gProj, 256, SMEM_BYTES>>>(cc, wh + 3*(size_t)CC*CC,
        CC, CC, CC, 0, 0, 0, bo, 1.f, nullptr, out, CC);
}

// round 14
// speedup vs baseline: 2.4992x; 1.0382x over previous
#include <cuda_runtime.h>
#include <cuda_fp16.h>
#include <cstdint>
#include <cstddef>

typedef unsigned int u32;
typedef unsigned short u16;

#define BN 4
#define TT 2048
#define CC 1024
#define MROWS (BN*TT)   // 8192

// ======================= device scratch (no allocs allowed) =======================
__device__ __align__(256) __half g_xh[MROWS*CC];
__device__ __align__(256) __half g_wh[4*CC*CC];
__device__ __align__(256) __half g_q [MROWS*CC];
__device__ __align__(256) __half g_k [MROWS*CC];
__device__ __align__(256) __half g_vt[MROWS*CC];                 // V^T [b][d][s]
__device__ __align__(256) float  g_s [(size_t)BN*TT*TT];
__device__ __align__(256) __half g_p [(size_t)BN*TT*TT];
__device__ __align__(256) __half g_c [MROWS*CC];

// ======================= PTX helpers (sm_100 baseline, NO 'a' features) =======================
__device__ __forceinline__ u32 smem_u32(const void* p) {
    u32 a;
    asm("{ .reg .u64 t; cvta.to.shared.u64 t, %1; cvt.u32.u64 %0, t; }" : "=r"(a) : "l"(p));
    return a;
}
__device__ __forceinline__ void cpa16(u32 dst, const void* src) {
    asm volatile("cp.async.cg.shared.global [%0], [%1], 16;" :: "r"(dst), "l"(src) : "memory");
}
#define CP_COMMIT() asm volatile("cp.async.commit_group;" ::: "memory")
#define CP_WAIT(n)  asm volatile("cp.async.wait_group %0;" :: "n"(n) : "memory")

#define LDSM4(d0,d1,d2,d3,a) \
    asm volatile("ldmatrix.sync.aligned.m8n8.x4.shared.b16 {%0,%1,%2,%3}, [%4];" \
                 : "=r"(d0),"=r"(d1),"=r"(d2),"=r"(d3) : "r"(a))

__device__ __forceinline__ void mma_f16(float* c, const u32* a, const u32* b) {
    asm volatile(
        "mma.sync.aligned.m16n8k16.row.col.f32.f16.f16.f32 "
        "{%0,%1,%2,%3}, {%4,%5,%6,%7}, {%8,%9}, {%0,%1,%2,%3};"
        : "+f"(c[0]), "+f"(c[1]), "+f"(c[2]), "+f"(c[3])
        : "r"(a[0]), "r"(a[1]), "r"(a[2]), "r"(a[3]), "r"(b[0]), "r"(b[1]));
}

__device__ __forceinline__ u32 pack_h2(__half a, __half b) {
    __half2 t = __halves2half2(a, b);
    return *reinterpret_cast<u32*>(&t);
}
__device__ __forceinline__ u16 h_bits(__half h) {
    return *reinterpret_cast<u16*>(&h);
}

// ======================= GEMM kernel =======================
// Tile 128x128, K-chunk 64 (half). Stage row = 64 halves = 128B (full SW128).
// Stage: A(16K) + B(16K) = 32KB; 2 stages = 64KB + 1KB hdr -> 2 CTAs/SM.
#define ST_BYTES   32768u
#define NSTAGE     2
#define SMEM_BYTES (1024 + NSTAGE*32768)   // 66560

// MODE 0: half out (+optional bias, +batch stride on C)         [Q,K,P->ctx]
// MODE 1: V-projection: bias then transposed half store into vt[b][d][s]
// MODE 2: fp32 * scale out (+batch stride on C)                 [scores]
// MODE 3: fp32 + bias out (final output)
template<int MODE>
__global__ void __launch_bounds__(256, 2) gemm_f16(
    const __half* __restrict__ A, const __half* __restrict__ B,
    int lda, int ldb, int K,
    long long sAz, long long sBz, long long sCz,
    const float* __restrict__ bias, float scale,
    __half* __restrict__ outH, float* __restrict__ outF, int ldc)
{
    extern __shared__ __align__(1024) char smem_raw[];
    const u32 sb0 = smem_u32(smem_raw);
    const u32 sb  = (sb0 + 1023u) & ~1023u;
    char* smem_ptr = smem_raw + (sb - sb0);

    const int tid  = threadIdx.x;
    const int lane = tid & 31, wid = tid >> 5;
    const int wm = wid & 1, wn = wid >> 1;          // 2 x 4 warp grid
    const int m0 = blockIdx.x * 128, n0 = blockIdx.y * 128;
    const long long z = blockIdx.z;
    A += z * sAz; B += z * sBz;

    float acc[4][4][4];
    #pragma unroll
    for (int i = 0; i < 4; ++i)
        #pragma unroll
        for (int j = 0; j < 4; ++j)
            #pragma unroll
            for (int e = 0; e < 4; ++e) acc[i][j][e] = 0.f;

    // ---- cp.async loader: thread t -> row t/2 (0..127), 4x16B chunks at c16=(t&1)*4 ----
    const int lr  = tid >> 1;
    const int lc0 = (tid & 1) * 4;
    const __half* gA = A + (size_t)(m0 + lr) * lda + lc0 * 8;
    const __half* gB = B + (size_t)(n0 + lr) * ldb + lc0 * 8;
    u32 swoff[4];
    #pragma unroll
    for (int j = 0; j < 4; ++j)
        swoff[j] = (u32)lr * 128u + (u32)(((lc0 + j) ^ (lr & 7)) << 4);

    auto load_stage = [&](int s, int k0) {          // k0 in half elements
        const u32 b = sb + (u32)s * ST_BYTES;
        #pragma unroll
        for (int j = 0; j < 4; ++j) {
            cpa16(b +           swoff[j], gA + k0 + j * 8);
            cpa16(b + 16384u +  swoff[j], gB + k0 + j * 8);
        }
        CP_COMMIT();
    };

    const int nch = K >> 6;
    load_stage(0, 0);

    // ---- ldmatrix lane maps ----
    const int rr = lane & 7;
    // A x4: rows rA = lane&15, col-parity cA = lane>>4; rA&7 == rr
    const int rA = lane & 15, cA = lane >> 4;
    const u32 aBase = (u32)(wm * 64 + rA) * 128u;
    // B x4 pair load: lane group g: row = wn*32 + (g>>1)*8 + rr, col-parity g&1
    const int g   = lane >> 3;
    const int gB1 = g & 1;
    const u32 bBase = (u32)(wn * 32 + ((g >> 1) << 3) + rr) * 128u;
    u32 cAo[4], cBo[4];
    #pragma unroll
    for (int ks = 0; ks < 4; ++ks) {
        cAo[ks] = (u32)(((ks * 2 + cA)  ^ rr) << 4);
        cBo[ks] = (u32)(((ks * 2 + gB1) ^ rr) << 4);
    }

    for (int c = 0; c < nch; ++c) {
        CP_WAIT(0);          // chunk c's data resident
        __syncthreads();     // + all warps done with stage (c-1)%2
        if (c + 1 < nch)     // prefetch c+1 into the freed stage; covered by c's compute
            load_stage((c + 1) & 1, (c + 1) * 64);

        const u32 base  = sb + (u32)(c & 1) * ST_BYTES;
        const u32 baseB = base + 16384u;
        #pragma unroll
        for (int ks = 0; ks < 4; ++ks) {
            u32 bb[4][2];
            LDSM4(bb[0][0], bb[0][1], bb[1][0], bb[1][1], baseB + bBase +          cBo[ks]);
            LDSM4(bb[2][0], bb[2][1], bb[3][0], bb[3][1], baseB + bBase + 2048u + cBo[ks]);
            #pragma unroll
            for (int am = 0; am < 4; ++am) {
                u32 aa[4];
                LDSM4(aa[0], aa[1], aa[2], aa[3], base + aBase + (u32)am * 2048u + cAo[ks]);
                #pragma unroll
                for (int bn = 0; bn < 4; ++bn)
                    mma_f16(acc[am][bn], aa, bb[bn]);
            }
        }
    }

    // ======================= epilogue =======================
    const int q = lane >> 2, tq = lane & 3;

    if constexpr (MODE == 1) {
        __syncthreads();   // all warps done with stage smem before T-buffer overwrite
        // transpose 128x128 tile through smem (u16 = half bits), stride 132
        u16* T = reinterpret_cast<u16*>(smem_ptr);
        #pragma unroll
        for (int am = 0; am < 4; ++am)
            #pragma unroll
            for (int bn = 0; bn < 4; ++bn)
                #pragma unroll
                for (int e = 0; e < 4; ++e) {
                    const int ml = wm * 64 + am * 16 + q + (e >> 1) * 8;
                    const int nl = wn * 32 + bn * 8 + 2 * tq + (e & 1);
                    T[nl * 132 + ml] = h_bits(__float2half_rn(acc[am][bn][e] + bias[n0 + nl]));
                }
        __syncthreads();
        const int d  = tid >> 1;
        const int mh = (tid & 1) * 64;
        const int b  = m0 >> 11;
        const size_t idx = ((size_t)b * CC + (n0 + d)) * TT + (m0 & 2047) + mh;
        #pragma unroll
        for (int i = 0; i < 64; i += 8) {
            u32 w[4];
            #pragma unroll
            for (int p = 0; p < 4; ++p) {
                const u32 t0 = (u32)T[d * 132 + mh + i + 2 * p];
                const u32 t1 = (u32)T[d * 132 + mh + i + 2 * p + 1];
                w[p] = t0 | (t1 << 16);
            }
            *reinterpret_cast<uint4*>(outH + idx + i) = make_uint4(w[0], w[1], w[2], w[3]);
        }
        return;
    } else {

    if (MODE == 0) outH += z * sCz;
    else           outF += z * sCz;

    #pragma unroll
    for (int am = 0; am < 4; ++am)
        #pragma unroll
        for (int e2 = 0; e2 < 2; ++e2) {
            const int gm = m0 + wm * 64 + am * 16 + q + e2 * 8;
            #pragma unroll
            for (int bn = 0; bn < 4; ++bn) {
                const int gn = n0 + wn * 32 + bn * 8 + 2 * tq;
                float v0 = acc[am][bn][e2 * 2 + 0];
                float v1 = acc[am][bn][e2 * 2 + 1];
                if (MODE == 0) {
                    if (bias) { v0 += bias[gn]; v1 += bias[gn + 1]; }
                    *reinterpret_cast<u32*>(outH + (size_t)gm * ldc + gn) =
                        pack_h2(__float2half_rn(v0), __float2half_rn(v1));
                } else if (MODE == 2) {
                    float2 val; val.x = v0 * scale; val.y = v1 * scale;
                    *reinterpret_cast<float2*>(outF + (size_t)gm * ldc + gn) = val;
                } else {
                    float2 val; val.x = v0 + bias[gn]; val.y = v1 + bias[gn + 1];
                    *reinterpret_cast<float2*>(outF + (size_t)gm * ldc + gn) = val;
                }
            }
        }
    }
}

// ======================= convert fp32 -> half =======================
__global__ void __launch_bounds__(256) cvt_kernel(
    const float* __restrict__ x, __half* __restrict__ o, int n4)
{
    int i = blockIdx.x * 256 + threadIdx.x;
    if (i >= n4) return;
    float4 v = reinterpret_cast<const float4*>(x)[i];
    uint2 w;
    w.x = pack_h2(__float2half_rn(v.x), __float2half_rn(v.y));
    w.y = pack_h2(__float2half_rn(v.z), __float2half_rn(v.w));
    *reinterpret_cast<uint2*>(o + 4*(size_t)i) = w;
}

__global__ void __launch_bounds__(256) cvt_w4_kernel(
    const float* __restrict__ w0, const float* __restrict__ w1,
    const float* __restrict__ w2, const float* __restrict__ w3,
    __half* __restrict__ o)
{
    const int mat = blockIdx.y;
    const float* src = (mat == 0) ? w0 : (mat == 1) ? w1 : (mat == 2) ? w2 : w3;
    const size_t off = (size_t)mat * CC * CC;
    int i = blockIdx.x * 256 + threadIdx.x;
    float4 v = reinterpret_cast<const float4*>(src)[i];
    uint2 w;
    w.x = pack_h2(__float2half_rn(v.x), __float2half_rn(v.y));
    w.y = pack_h2(__float2half_rn(v.z), __float2half_rn(v.w));
    *reinterpret_cast<uint2*>(o + off + 4*(size_t)i) = w;
}

// ======================= softmax (fp32 in, half out) =======================
__global__ void __launch_bounds__(256) softmax_kernel(
    const float* __restrict__ S, __half* __restrict__ P)
{
    __shared__ float red[8];
    __shared__ float sM, sInv;
    const size_t row = blockIdx.x;
    const float4* src = reinterpret_cast<const float4*>(S + row * TT);
    const int t = threadIdx.x, w = t >> 5, ln = t & 31;

    float4 a = src[t], b2 = src[t + 256];
    float mx = fmaxf(fmaxf(fmaxf(a.x, a.y), fmaxf(a.z, a.w)),
                     fmaxf(fmaxf(b2.x, b2.y), fmaxf(b2.z, b2.w)));
    #pragma unroll
    for (int o = 16; o; o >>= 1) mx = fmaxf(mx, __shfl_xor_sync(0xffffffffu, mx, o));
    if (ln == 0) red[w] = mx;
    __syncthreads();
    if (t == 0) {
        float m = red[0];
        #pragma unroll
        for (int i = 1; i < 8; ++i) m = fmaxf(m, red[i]);
        sM = m;
    }
    __syncthreads();
    const float M = sM;

    float e[8];
    e[0] = __expf(a.x - M);  e[1] = __expf(a.y - M);
    e[2] = __expf(a.z - M);  e[3] = __expf(a.w - M);
    e[4] = __expf(b2.x - M); e[5] = __expf(b2.y - M);
    e[6] = __expf(b2.z - M); e[7] = __expf(b2.w - M);
    float sm = e[0]+e[1]+e[2]+e[3]+e[4]+e[5]+e[6]+e[7];
    #pragma unroll
    for (int o = 16; o; o >>= 1) sm += __shfl_xor_sync(0xffffffffu, sm, o);
    __syncthreads();
    if (ln == 0) red[w] = sm;
    __syncthreads();
    if (t == 0) {
        float ssum = 0.f;
        #pragma unroll
        for (int i = 0; i < 8; ++i) ssum += red[i];
        sInv = 1.0f / ssum;
    }
    __syncthreads();
    const float inv = sInv;

    #pragma unroll
    for (int half = 0; half < 2; ++half) {
        uint2 w2o;
        w2o.x = pack_h2(__float2half_rn(e[half*4 + 0] * inv), __float2half_rn(e[half*4 + 1] * inv));
        w2o.y = pack_h2(__float2half_rn(e[half*4 + 2] * inv), __float2half_rn(e[half*4 + 3] * inv));
        size_t off = row * TT + (size_t)(t + half*256) * 4;
        *reinterpret_cast<uint2*>(P + off) = w2o;
    }
}

// ======================= host launch =======================
static void* sym_addr(const void* s) {
    void* p = nullptr;
    cudaGetSymbolAddress(&p, s);
    return p;
}

extern "C" void kernel_launch(void* const* d_in, const int* in_sizes, int n_in,
                              void* d_out, int out_size) {
    (void)in_sizes; (void)n_in; (void)out_size;
    const float* x  = (const float*)d_in[0];
    const float* Wq = (const float*)d_in[1];
    const float* bq = (const float*)d_in[2];
    const float* Wk = (const float*)d_in[3];
    const float* bk = (const float*)d_in[4];
    const float* Wv = (const float*)d_in[5];
    const float* bv = (const float*)d_in[6];
    const float* Wo = (const float*)d_in[7];
    const float* bo = (const float*)d_in[8];
    float* out = (float*)d_out;

    __half* xh = (__half*)sym_addr(g_xh);
    __half* wh = (__half*)sym_addr(g_wh);
    __half* qq = (__half*)sym_addr(g_q);
    __half* kk = (__half*)sym_addr(g_k);
    __half* vt = (__half*)sym_addr(g_vt);
    float*  sS = (float*)sym_addr(g_s);
    __half* pp = (__half*)sym_addr(g_p);
    __half* cc = (__half*)sym_addr(g_c);

    cudaFuncSetAttribute(gemm_f16<0>, cudaFuncAttributeMaxDynamicSharedMemorySize, SMEM_BYTES);
    cudaFuncSetAttribute(gemm_f16<1>, cudaFuncAttributeMaxDynamicSharedMemorySize, SMEM_BYTES);
    cudaFuncSetAttribute(gemm_f16<2>, cudaFuncAttributeMaxDynamicSharedMemorySize, SMEM_BYTES);
    cudaFuncSetAttribute(gemm_f16<3>, cudaFuncAttributeMaxDynamicSharedMemorySize, SMEM_BYTES);

    // convert inputs to half
    cvt_kernel<<<(MROWS*CC/4 + 255)/256, 256>>>(x, xh, MROWS*CC/4);
    dim3 gW(CC*CC/4/256, 4);
    cvt_w4_kernel<<<gW, 256>>>(Wq, Wk, Wv, Wo, wh);

    dim3 gProj(MROWS/128, CC/128, 1);     // (64, 8, 1)
    // Q = x Wq^T + bq (half out)
    gemm_f16<0><<<gProj, 256, SMEM_BYTES>>>(xh, wh + 0*(size_t)CC*CC,
        CC, CC, CC, 0, 0, 0, bq, 1.f, qq, nullptr, CC);
    // K
    gemm_f16<0><<<gProj, 256, SMEM_BYTES>>>(xh, wh + 1*(size_t)CC*CC,
        CC, CC, CC, 0, 0, 0, bk, 1.f, kk, nullptr, CC);
    // V -> transposed half store vt[b][d][s]
    gemm_f16<1><<<gProj, 256, SMEM_BYTES>>>(xh, wh + 2*(size_t)CC*CC,
        CC, CC, CC, 0, 0, 0, bv, 1.f, vt, nullptr, 0);

    // scores = Q K^T / 32 (per batch, fp32 out)
    dim3 gScore(TT/128, TT/128, BN);      // (16, 16, 4)
    gemm_f16<2><<<gScore, 256, SMEM_BYTES>>>(qq, kk,
        CC, CC, CC, (long long)TT*CC, (long long)TT*CC, (long long)TT*TT,
        nullptr, 0.03125f, nullptr, sS, TT);

    // softmax (writes half P)
    softmax_kernel<<<MROWS, 256>>>(sS, pp);

    // ctx = P V (A = P [t][s], B = vt [d][s], per batch; half out)
    dim3 gPV(TT/128, CC/128, BN);         // (16, 8, 4)
    gemm_f16<0><<<gPV, 256, SMEM_BYTES>>>(pp, vt,
        TT, TT, TT, (long long)TT*TT, (long long)CC*TT, (long long)TT*CC,
        nullptr, 1.f, cc, nullptr, CC);

    // out = ctx Wo^T + bo (fp32 -> d_out)
    gemm_f16<3><<<gProj, 256, SMEM_BYTES>>>(cc, wh + 3*(size_t)CC*CC,
        CC, CC, CC, 0, 0, 0, bo, 1.f, nullptr, out, CC);
}